// round 1
// baseline (speedup 1.0000x reference)
#include <cuda_runtime.h>
#include <cuda_bf16.h>
#include <cstdint>

// ---------------------------------------------------------------------------
// Problem constants (fixed shapes)
// ---------------------------------------------------------------------------
#define NN   8192     // nodes
#define FIN  128
#define FHID 64
#define FOUT 2

// ---------------------------------------------------------------------------
// Scratch (__device__ globals -- sanctioned workaround, no runtime allocs)
// ---------------------------------------------------------------------------
__device__ __nv_bfloat16 g_adjb[(size_t)NN * NN];   // 128 MB bf16 adjacency
__device__ float         g_d[NN];                    // d_inv_sqrt
__device__ __nv_bfloat16 g_z1[NN * FHID];            // d ⊙ (x@W1), bf16 [8192,64]
__device__ __nv_bfloat16 g_z2[NN * 8];               // d ⊙ (h@W2), bf16 [8192,8] (N padded 2->8)

// ---------------------------------------------------------------------------
// Small PTX helpers
// ---------------------------------------------------------------------------
__device__ __forceinline__ unsigned smem_u32(const void* p) {
    return (unsigned)__cvta_generic_to_shared(p);
}
__device__ __forceinline__ void cp16(void* dst, const void* src) {
    unsigned d = smem_u32(dst);
    asm volatile("cp.async.cg.shared.global [%0],[%1],16;\n" :: "r"(d), "l"(src));
}
__device__ __forceinline__ void cp_commit() {
    asm volatile("cp.async.commit_group;\n");
}
__device__ __forceinline__ void cp_wait_all() {
    asm volatile("cp.async.wait_group 0;\n");
}
__device__ __forceinline__ void ldmatrix_x4(uint32_t& a0, uint32_t& a1, uint32_t& a2, uint32_t& a3,
                                            unsigned addr) {
    asm volatile("ldmatrix.sync.aligned.m8n8.x4.shared.b16 {%0,%1,%2,%3},[%4];\n"
                 : "=r"(a0), "=r"(a1), "=r"(a2), "=r"(a3) : "r"(addr));
}
__device__ __forceinline__ void ldmatrix_x2_trans(uint32_t& b0, uint32_t& b1, unsigned addr) {
    asm volatile("ldmatrix.sync.aligned.m8n8.x2.trans.shared.b16 {%0,%1},[%2];\n"
                 : "=r"(b0), "=r"(b1) : "r"(addr));
}
__device__ __forceinline__ void mma_bf16(float c[4],
                                         uint32_t a0, uint32_t a1, uint32_t a2, uint32_t a3,
                                         uint32_t b0, uint32_t b1) {
    asm volatile("mma.sync.aligned.m16n8k16.row.col.f32.bf16.bf16.f32 "
                 "{%0,%1,%2,%3},{%4,%5,%6,%7},{%8,%9},{%0,%1,%2,%3};\n"
                 : "+f"(c[0]), "+f"(c[1]), "+f"(c[2]), "+f"(c[3])
                 : "r"(a0), "r"(a1), "r"(a2), "r"(a3), "r"(b0), "r"(b1));
}
__device__ __forceinline__ unsigned bf2_bits(__nv_bfloat162 v) {
    return *reinterpret_cast<unsigned*>(&v);
}

// ---------------------------------------------------------------------------
// Kernel 1: row sums of adj (fp32, exact) + convert adj -> bf16 scratch.
// One block per row; 256 threads stride 8192 cols via float4.
// ---------------------------------------------------------------------------
__global__ __launch_bounds__(256) void k_rowsum_convert(const float* __restrict__ adj) {
    int row = blockIdx.x;
    const float4* src = reinterpret_cast<const float4*>(adj + (size_t)row * NN);
    uint2* dst = reinterpret_cast<uint2*>(g_adjb + (size_t)row * NN);
    float s = 0.f;
#pragma unroll
    for (int it = 0; it < 8; ++it) {
        int idx = it * 256 + threadIdx.x;
        float4 v = src[idx];
        s += (v.x + v.y) + (v.z + v.w);
        __nv_bfloat162 lo = __floats2bfloat162_rn(v.x, v.y);
        __nv_bfloat162 hi = __floats2bfloat162_rn(v.z, v.w);
        uint2 o;
        o.x = bf2_bits(lo);
        o.y = bf2_bits(hi);
        dst[idx] = o;
    }
    // block reduce
    for (int o = 16; o; o >>= 1) s += __shfl_xor_sync(0xFFFFFFFFu, s, o);
    __shared__ float ws[8];
    if ((threadIdx.x & 31) == 0) ws[threadIdx.x >> 5] = s;
    __syncthreads();
    if (threadIdx.x == 0) {
        float t = 0.f;
#pragma unroll
        for (int w = 0; w < 8; ++w) t += ws[w];
        g_d[row] = rsqrtf(t + 1e-6f);
    }
}

// ---------------------------------------------------------------------------
// Kernel 2: z1 = bf16( d ⊙ (x @ W1) ).  16 rows per block, W1 staged in smem.
// ---------------------------------------------------------------------------
__global__ __launch_bounds__(256) void k_xw1(const float* __restrict__ x,
                                             const float* __restrict__ W1) {
    __shared__ float W1s[FIN][FHID];   // 32 KB
    __shared__ float xs[16][FIN];      // 8 KB
    int tid = threadIdx.x;
    int r0 = blockIdx.x * 16;
    for (int i = tid; i < FIN * FHID; i += 256) W1s[i >> 6][i & 63] = W1[i];
    for (int i = tid; i < 16 * FIN; i += 256) xs[i >> 7][i & 127] = x[(size_t)r0 * FIN + i];
    __syncthreads();
    int f = tid & 63;
    int rb = tid >> 6;   // 0..3
    float acc[4] = {0.f, 0.f, 0.f, 0.f};
#pragma unroll
    for (int k = 0; k < FIN; ++k) {
        float w = W1s[k][f];
#pragma unroll
        for (int j = 0; j < 4; ++j) acc[j] += xs[rb + j * 4][k] * w;
    }
#pragma unroll
    for (int j = 0; j < 4; ++j) {
        int row = r0 + rb + j * 4;
        g_z1[row * FHID + f] = __float2bfloat16(g_d[row] * acc[j]);
    }
}

// ---------------------------------------------------------------------------
// Kernel 3: agg1 + fused layer-1 epilogue + layer-2 small GEMM.
//   U = adjb @ z1  (M=8192, N=64, K=8192, bf16 MMA, fp32 accum)
//   h = relu(d*U + b1)   (in smem)
//   z2 = bf16( d ⊙ (h @ W2) ), padded N=8
// CTA tile: 64x64, K_TILE=64, 8 warps (2x4), warp tile 32x16.
// ---------------------------------------------------------------------------
struct MM3 {
    __nv_bfloat16 A[2][64][72];
    __nv_bfloat16 B[2][64][72];
};
union SM3 {
    MM3 mm;
    float h[64][66];
};

__global__ __launch_bounds__(256) void k_agg1(const float* __restrict__ b1,
                                              const float* __restrict__ W2) {
    __shared__ __align__(16) SM3 sm;
    int tid = threadIdx.x;
    int warp = tid >> 5, lane = tid & 31;
    int wm = warp >> 2, wn = warp & 3;            // 2 x 4 warp grid
    int row0 = blockIdx.x * 64;
    float acc[2][2][4] = {};

    const __nv_bfloat16* Ag = g_adjb + (size_t)row0 * NN;

    auto load_tiles = [&](int buf, int k0) {
#pragma unroll
        for (int i = 0; i < 2; ++i) {
            int c = tid + i * 256;        // 512 16B-chunks per tile
            int r = c >> 3, col = (c & 7) * 8;
            cp16(&sm.mm.A[buf][r][col], Ag + (size_t)r * NN + k0 + col);
            cp16(&sm.mm.B[buf][r][col], g_z1 + (size_t)(k0 + r) * FHID + col);
        }
        cp_commit();
    };

    load_tiles(0, 0);
    const int NIT = NN / 64;   // 128
    for (int it = 0; it < NIT; ++it) {
        cp_wait_all();
        __syncthreads();
        if (it + 1 < NIT) load_tiles((it + 1) & 1, (it + 1) * 64);
        int buf = it & 1;
#pragma unroll
        for (int ks = 0; ks < 4; ++ks) {
            uint32_t a[2][4], b[2][2];
#pragma unroll
            for (int mt = 0; mt < 2; ++mt) {
                unsigned ad = smem_u32(&sm.mm.A[buf][wm * 32 + mt * 16 + (lane & 15)]
                                                 [ks * 16 + (lane >> 4) * 8]);
                ldmatrix_x4(a[mt][0], a[mt][1], a[mt][2], a[mt][3], ad);
            }
#pragma unroll
            for (int nt = 0; nt < 2; ++nt) {
                unsigned bd = smem_u32(&sm.mm.B[buf][ks * 16 + (lane & 15)][wn * 16 + nt * 8]);
                ldmatrix_x2_trans(b[nt][0], b[nt][1], bd);
            }
#pragma unroll
            for (int mt = 0; mt < 2; ++mt)
#pragma unroll
                for (int nt = 0; nt < 2; ++nt)
                    mma_bf16(acc[mt][nt], a[mt][0], a[mt][1], a[mt][2], a[mt][3],
                             b[nt][0], b[nt][1]);
        }
    }
    __syncthreads();   // mainloop smem reads done before aliasing as h

    // h = relu(d*U + b1) into smem
#pragma unroll
    for (int mt = 0; mt < 2; ++mt) {
        int rbase = wm * 32 + mt * 16 + (lane >> 2);
#pragma unroll
        for (int nt = 0; nt < 2; ++nt) {
            int cbase = wn * 16 + nt * 8 + (lane & 3) * 2;
            float bb0 = b1[cbase], bb1 = b1[cbase + 1];
#pragma unroll
            for (int half = 0; half < 2; ++half) {
                int r = rbase + half * 8;
                float dd = g_d[row0 + r];
                sm.h[r][cbase]     = fmaxf(dd * acc[mt][nt][half * 2 + 0] + bb0, 0.f);
                sm.h[r][cbase + 1] = fmaxf(dd * acc[mt][nt][half * 2 + 1] + bb1, 0.f);
            }
        }
    }
    __syncthreads();

    // z2 = d ⊙ (h @ W2), one thread per row, write 8 bf16 (16B) padded
    if (tid < 64) {
        float s0 = 0.f, s1 = 0.f;
#pragma unroll
        for (int k = 0; k < FHID; ++k) {
            float hv = sm.h[tid][k];
            s0 += hv * W2[k * 2 + 0];
            s1 += hv * W2[k * 2 + 1];
        }
        int row = row0 + tid;
        float dd = g_d[row];
        __nv_bfloat162 p0 = __floats2bfloat162_rn(dd * s0, dd * s1);
        uint4 o;
        o.x = bf2_bits(p0);
        o.y = 0u; o.z = 0u; o.w = 0u;
        *reinterpret_cast<uint4*>(&g_z2[(size_t)row * 8]) = o;
    }
}

// ---------------------------------------------------------------------------
// Kernel 4: agg2: out = d ⊙ (adjb @ z2) + b2   (M=8192, N=8 padded, K=8192)
// CTA tile 128x8, K_TILE=64, 8 warps stacked (warp tile 16x8).
// ---------------------------------------------------------------------------
__global__ __launch_bounds__(256) void k_agg2(const float* __restrict__ b2,
                                              float* __restrict__ out) {
    __shared__ __align__(16) __nv_bfloat16 As[2][128][72];  // 36 KB
    __shared__ __align__(16) __nv_bfloat16 Bs[2][64][24];   // 6 KB
    int tid = threadIdx.x, warp = tid >> 5, lane = tid & 31;
    int row0 = blockIdx.x * 128;
    float acc[4] = {0.f, 0.f, 0.f, 0.f};
    const __nv_bfloat16* Ag = g_adjb + (size_t)row0 * NN;

    auto load_tiles = [&](int buf, int k0) {
#pragma unroll
        for (int i = 0; i < 4; ++i) {
            int c = tid + i * 256;       // 1024 chunks for A (128 rows x 128B)
            int r = c >> 3, col = (c & 7) * 8;
            cp16(&As[buf][r][col], Ag + (size_t)r * NN + k0 + col);
        }
        if (tid < 64) cp16(&Bs[buf][tid][0], g_z2 + (size_t)(k0 + tid) * 8);
        cp_commit();
    };

    load_tiles(0, 0);
    const int NIT = NN / 64;   // 128
    for (int it = 0; it < NIT; ++it) {
        cp_wait_all();
        __syncthreads();
        if (it + 1 < NIT) load_tiles((it + 1) & 1, (it + 1) * 64);
        int buf = it & 1;
#pragma unroll
        for (int ks = 0; ks < 4; ++ks) {
            uint32_t a0, a1, a2, a3, b0, b1r;
            unsigned ad = smem_u32(&As[buf][warp * 16 + (lane & 15)][ks * 16 + (lane >> 4) * 8]);
            ldmatrix_x4(a0, a1, a2, a3, ad);
            unsigned bd = smem_u32(&Bs[buf][ks * 16 + (lane & 15)][0]);
            ldmatrix_x2_trans(b0, b1r, bd);
            mma_bf16(acc, a0, a1, a2, a3, b0, b1r);
        }
    }

    // epilogue: cols 0,1 live in lanes with (lane&3)==0
    if ((lane & 3) == 0) {
        int r0 = warp * 16 + (lane >> 2);
        int gr = row0 + r0;
        float bb0 = b2[0], bb1 = b2[1];
        float d0 = g_d[gr];
        out[gr * 2 + 0] = d0 * acc[0] + bb0;
        out[gr * 2 + 1] = d0 * acc[1] + bb1;
        int gr2 = gr + 8;
        float d1 = g_d[gr2];
        out[gr2 * 2 + 0] = d1 * acc[2] + bb0;
        out[gr2 * 2 + 1] = d1 * acc[3] + bb1;
    }
}

// ---------------------------------------------------------------------------
// Launch
// ---------------------------------------------------------------------------
extern "C" void kernel_launch(void* const* d_in, const int* in_sizes, int n_in,
                              void* d_out, int out_size) {
    // Robust input mapping by element count (all sizes distinct).
    const float *x = nullptr, *adj = nullptr, *W1 = nullptr, *b1 = nullptr,
                *W2 = nullptr, *b2 = nullptr;
    for (int i = 0; i < n_in; ++i) {
        switch (in_sizes[i]) {
            case NN * FIN:        x   = (const float*)d_in[i]; break;   // 1048576
            case 67108864:        adj = (const float*)d_in[i]; break;   // 8192*8192
            case FIN * FHID:      W1  = (const float*)d_in[i]; break;   // 8192
            case FHID:            b1  = (const float*)d_in[i]; break;   // 64
            case FHID * FOUT:     W2  = (const float*)d_in[i]; break;   // 128
            case FOUT:            b2  = (const float*)d_in[i]; break;   // 2
            default: break;
        }
    }
    float* out = (float*)d_out;

    k_rowsum_convert<<<NN, 256>>>(adj);
    k_xw1<<<NN / 16, 256>>>(x, W1);
    k_agg1<<<NN / 64, 256>>>(b1, W2);
    k_agg2<<<NN / 128, 256>>>(b2, out);
}

// round 2
// speedup vs baseline: 1.8279x; 1.8279x over previous
#include <cuda_runtime.h>
#include <cuda_bf16.h>
#include <cstdint>

// ---------------------------------------------------------------------------
// Problem constants (fixed shapes)
// ---------------------------------------------------------------------------
#define NN   8192
#define FIN  128
#define FHID 64
#define FOUT 2
#define KSPLIT 4

// ---------------------------------------------------------------------------
// Scratch (__device__ globals -- sanctioned, no runtime allocs)
// ---------------------------------------------------------------------------
__device__ __nv_bfloat16 g_adjb[(size_t)NN * NN];   // 128 MB bf16 adjacency
__device__ float         g_d[NN];                    // d_inv_sqrt
__device__ __nv_bfloat16 g_z1[NN * FHID];            // d ⊙ (x@W1)  [8192,64]
__device__ __nv_bfloat16 g_z2[NN * 8];               // d ⊙ (h@W2)  [8192,8] (N pad 2->8)
__device__ float         g_part[KSPLIT][NN][2];      // split-K partials for layer 2

// ---------------------------------------------------------------------------
// PTX helpers
// ---------------------------------------------------------------------------
__device__ __forceinline__ unsigned smem_u32(const void* p) {
    return (unsigned)__cvta_generic_to_shared(p);
}
__device__ __forceinline__ void cp16(void* dst, const void* src) {
    unsigned d = smem_u32(dst);
    asm volatile("cp.async.cg.shared.global [%0],[%1],16;\n" :: "r"(d), "l"(src));
}
__device__ __forceinline__ void cp_commit() {
    asm volatile("cp.async.commit_group;\n");
}
__device__ __forceinline__ void cp_wait_2() {
    asm volatile("cp.async.wait_group 2;\n");
}
__device__ __forceinline__ void cp_wait_all() {
    asm volatile("cp.async.wait_group 0;\n");
}
__device__ __forceinline__ void ldmatrix_x4(uint32_t& a0, uint32_t& a1, uint32_t& a2, uint32_t& a3,
                                            unsigned addr) {
    asm volatile("ldmatrix.sync.aligned.m8n8.x4.shared.b16 {%0,%1,%2,%3},[%4];\n"
                 : "=r"(a0), "=r"(a1), "=r"(a2), "=r"(a3) : "r"(addr));
}
__device__ __forceinline__ void ldmatrix_x2_trans(uint32_t& b0, uint32_t& b1, unsigned addr) {
    asm volatile("ldmatrix.sync.aligned.m8n8.x2.trans.shared.b16 {%0,%1},[%2];\n"
                 : "=r"(b0), "=r"(b1) : "r"(addr));
}
__device__ __forceinline__ void mma_bf16(float c[4],
                                         uint32_t a0, uint32_t a1, uint32_t a2, uint32_t a3,
                                         uint32_t b0, uint32_t b1) {
    asm volatile("mma.sync.aligned.m16n8k16.row.col.f32.bf16.bf16.f32 "
                 "{%0,%1,%2,%3},{%4,%5,%6,%7},{%8,%9},{%0,%1,%2,%3};\n"
                 : "+f"(c[0]), "+f"(c[1]), "+f"(c[2]), "+f"(c[3])
                 : "r"(a0), "r"(a1), "r"(a2), "r"(a3), "r"(b0), "r"(b1));
}
__device__ __forceinline__ unsigned bf2_bits(__nv_bfloat162 v) {
    return *reinterpret_cast<unsigned*>(&v);
}

// ---------------------------------------------------------------------------
// Kernel 1: row sums of adj (fp32, exact) + convert adj -> bf16 scratch.
// ---------------------------------------------------------------------------
__global__ __launch_bounds__(256) void k_rowsum_convert(const float* __restrict__ adj) {
    int row = blockIdx.x;
    const float4* src = reinterpret_cast<const float4*>(adj + (size_t)row * NN);
    uint2* dst = reinterpret_cast<uint2*>(g_adjb + (size_t)row * NN);
    float s = 0.f;
#pragma unroll
    for (int it = 0; it < 8; ++it) {
        int idx = it * 256 + threadIdx.x;
        float4 v = src[idx];
        s += (v.x + v.y) + (v.z + v.w);
        __nv_bfloat162 lo = __floats2bfloat162_rn(v.x, v.y);
        __nv_bfloat162 hi = __floats2bfloat162_rn(v.z, v.w);
        uint2 o;
        o.x = bf2_bits(lo);
        o.y = bf2_bits(hi);
        dst[idx] = o;
    }
    for (int o = 16; o; o >>= 1) s += __shfl_xor_sync(0xFFFFFFFFu, s, o);
    __shared__ float ws[8];
    if ((threadIdx.x & 31) == 0) ws[threadIdx.x >> 5] = s;
    __syncthreads();
    if (threadIdx.x == 0) {
        float t = 0.f;
#pragma unroll
        for (int w = 0; w < 8; ++w) t += ws[w];
        g_d[row] = rsqrtf(t + 1e-6f);
    }
}

// ---------------------------------------------------------------------------
// Kernel 2: z1 = bf16( d ⊙ (x @ W1) ).
// ---------------------------------------------------------------------------
__global__ __launch_bounds__(256) void k_xw1(const float* __restrict__ x,
                                             const float* __restrict__ W1) {
    __shared__ float W1s[FIN][FHID];
    __shared__ float xs[16][FIN];
    int tid = threadIdx.x;
    int r0 = blockIdx.x * 16;
    for (int i = tid; i < FIN * FHID; i += 256) W1s[i >> 6][i & 63] = W1[i];
    for (int i = tid; i < 16 * FIN; i += 256) xs[i >> 7][i & 127] = x[(size_t)r0 * FIN + i];
    __syncthreads();
    int f = tid & 63;
    int rb = tid >> 6;
    float acc[4] = {0.f, 0.f, 0.f, 0.f};
#pragma unroll
    for (int k = 0; k < FIN; ++k) {
        float w = W1s[k][f];
#pragma unroll
        for (int j = 0; j < 4; ++j) acc[j] += xs[rb + j * 4][k] * w;
    }
#pragma unroll
    for (int j = 0; j < 4; ++j) {
        int row = r0 + rb + j * 4;
        g_z1[row * FHID + f] = __float2bfloat16(g_d[row] * acc[j]);
    }
}

// ---------------------------------------------------------------------------
// Kernel 3: agg1 + fused epilogue: U = adjb @ z1 (8192x64x8192, bf16 MMA),
//           h = relu(d*U+b1) in smem, z2 = bf16(d ⊙ (h@W2)) padded to N=8.
// CTA tile 64x64, K_TILE=64, 4-stage cp.async pipeline, 8 warps (2x4).
// Dynamic smem: A[4][64][72] + B[4][64][72] bf16 = 73728 B; aliased h[64][66] f32.
// ---------------------------------------------------------------------------
#define KT 64
#define ST 4

__global__ __launch_bounds__(256) void k_agg1(const float* __restrict__ b1,
                                              const float* __restrict__ W2) {
    extern __shared__ __align__(16) unsigned char dyn[];
    __nv_bfloat16* Abuf = reinterpret_cast<__nv_bfloat16*>(dyn);     // [ST][64][72]
    __nv_bfloat16* Bbuf = Abuf + ST * 64 * 72;                        // [ST][64][72]
    float* hbuf = reinterpret_cast<float*>(dyn);                      // [64][66] alias

    int tid = threadIdx.x;
    int warp = tid >> 5, lane = tid & 31;
    int wm = warp >> 2, wn = warp & 3;
    int row0 = blockIdx.x * 64;
    float acc[2][2][4] = {};
    const __nv_bfloat16* Ag = g_adjb + (size_t)row0 * NN;

    auto load_tiles = [&](int s, int k0) {
        __nv_bfloat16* As = Abuf + s * 64 * 72;
        __nv_bfloat16* Bs = Bbuf + s * 64 * 72;
#pragma unroll
        for (int i = 0; i < 2; ++i) {
            int c = tid + i * 256;
            int r = c >> 3, col = (c & 7) * 8;
            cp16(As + r * 72 + col, Ag + (size_t)r * NN + k0 + col);
            cp16(Bs + r * 72 + col, g_z1 + (size_t)(k0 + r) * FHID + col);
        }
    };

#pragma unroll
    for (int s = 0; s < ST - 1; ++s) { load_tiles(s, s * KT); cp_commit(); }

    const int NIT = NN / KT;   // 128
    for (int it = 0; it < NIT; ++it) {
        cp_wait_2();
        __syncthreads();
        if (it + ST - 1 < NIT) load_tiles((it + ST - 1) & (ST - 1), (it + ST - 1) * KT);
        cp_commit();   // empty-group at tail keeps wait_group accounting exact
        int s = it & (ST - 1);
        __nv_bfloat16* As = Abuf + s * 64 * 72;
        __nv_bfloat16* Bs = Bbuf + s * 64 * 72;
#pragma unroll
        for (int ks = 0; ks < 4; ++ks) {
            uint32_t a[2][4], b[2][2];
#pragma unroll
            for (int mt = 0; mt < 2; ++mt) {
                unsigned ad = smem_u32(As + (wm * 32 + mt * 16 + (lane & 15)) * 72
                                          + ks * 16 + (lane >> 4) * 8);
                ldmatrix_x4(a[mt][0], a[mt][1], a[mt][2], a[mt][3], ad);
            }
#pragma unroll
            for (int nt = 0; nt < 2; ++nt) {
                unsigned bd = smem_u32(Bs + (ks * 16 + (lane & 15)) * 72 + wn * 16 + nt * 8);
                ldmatrix_x2_trans(b[nt][0], b[nt][1], bd);
            }
#pragma unroll
            for (int mt = 0; mt < 2; ++mt)
#pragma unroll
                for (int nt = 0; nt < 2; ++nt)
                    mma_bf16(acc[mt][nt], a[mt][0], a[mt][1], a[mt][2], a[mt][3],
                             b[nt][0], b[nt][1]);
        }
        __syncthreads();
    }
    cp_wait_all();
    __syncthreads();

    // h = relu(d*U + b1) into smem (aliases pipeline buffers, all reads done)
#pragma unroll
    for (int mt = 0; mt < 2; ++mt) {
        int rbase = wm * 32 + mt * 16 + (lane >> 2);
#pragma unroll
        for (int nt = 0; nt < 2; ++nt) {
            int cbase = wn * 16 + nt * 8 + (lane & 3) * 2;
            float bb0 = b1[cbase], bb1 = b1[cbase + 1];
#pragma unroll
            for (int half = 0; half < 2; ++half) {
                int r = rbase + half * 8;
                float dd = g_d[row0 + r];
                hbuf[r * 66 + cbase]     = fmaxf(dd * acc[mt][nt][half * 2 + 0] + bb0, 0.f);
                hbuf[r * 66 + cbase + 1] = fmaxf(dd * acc[mt][nt][half * 2 + 1] + bb1, 0.f);
            }
        }
    }
    __syncthreads();

    if (tid < 64) {
        float s0 = 0.f, s1 = 0.f;
#pragma unroll
        for (int k = 0; k < FHID; ++k) {
            float hv = hbuf[tid * 66 + k];
            s0 += hv * W2[k * 2 + 0];
            s1 += hv * W2[k * 2 + 1];
        }
        int row = row0 + tid;
        float dd = g_d[row];
        __nv_bfloat162 p0 = __floats2bfloat162_rn(dd * s0, dd * s1);
        uint4 o;
        o.x = bf2_bits(p0);
        o.y = 0u; o.z = 0u; o.w = 0u;
        *reinterpret_cast<uint4*>(&g_z2[(size_t)row * 8]) = o;
    }
}

// ---------------------------------------------------------------------------
// Kernel 4: agg2 split-K: partial[kslice] = adjb[rows, kslice-range] @ z2
//   M_TILE=64, K range 2048 per slice, K_TILE=64, 4-stage pipeline, 4 warps.
// Dynamic smem: A[4][64][72] + B[4][64][24] bf16 = 49152 B.
// ---------------------------------------------------------------------------
__global__ __launch_bounds__(128) void k_agg2() {
    extern __shared__ __align__(16) unsigned char dyn[];
    __nv_bfloat16* Abuf = reinterpret_cast<__nv_bfloat16*>(dyn);   // [ST][64][72]
    __nv_bfloat16* Bbuf = Abuf + ST * 64 * 72;                      // [ST][64][24]

    int tid = threadIdx.x, warp = tid >> 5, lane = tid & 31;
    int row0 = blockIdx.x * 64;
    int kslice = blockIdx.y;
    int kbase = kslice * (NN / KSPLIT);   // 2048
    float acc[4] = {0.f, 0.f, 0.f, 0.f};
    const __nv_bfloat16* Ag = g_adjb + (size_t)row0 * NN;

    auto load_tiles = [&](int s, int k0) {
        __nv_bfloat16* As = Abuf + s * 64 * 72;
        __nv_bfloat16* Bs = Bbuf + s * 64 * 24;
#pragma unroll
        for (int i = 0; i < 4; ++i) {
            int c = tid + i * 128;
            int r = c >> 3, col = (c & 7) * 8;
            cp16(As + r * 72 + col, Ag + (size_t)r * NN + k0 + col);
        }
        if (tid < 64) cp16(Bs + tid * 24, g_z2 + (size_t)(k0 + tid) * 8);
    };

#pragma unroll
    for (int s = 0; s < ST - 1; ++s) { load_tiles(s, kbase + s * KT); cp_commit(); }

    const int NIT = (NN / KSPLIT) / KT;   // 32
    for (int it = 0; it < NIT; ++it) {
        cp_wait_2();
        __syncthreads();
        if (it + ST - 1 < NIT) load_tiles((it + ST - 1) & (ST - 1), kbase + (it + ST - 1) * KT);
        cp_commit();
        int s = it & (ST - 1);
        __nv_bfloat16* As = Abuf + s * 64 * 72;
        __nv_bfloat16* Bs = Bbuf + s * 64 * 24;
#pragma unroll
        for (int ks = 0; ks < 4; ++ks) {
            uint32_t a0, a1, a2, a3, b0, b1r;
            unsigned ad = smem_u32(As + (warp * 16 + (lane & 15)) * 72
                                      + ks * 16 + (lane >> 4) * 8);
            ldmatrix_x4(a0, a1, a2, a3, ad);
            unsigned bd = smem_u32(Bs + (ks * 16 + (lane & 15)) * 24);
            ldmatrix_x2_trans(b0, b1r, bd);
            mma_bf16(acc, a0, a1, a2, a3, b0, b1r);
        }
        __syncthreads();
    }

    if ((lane & 3) == 0) {
        int r = warp * 16 + (lane >> 2);
        g_part[kslice][row0 + r][0] = acc[0];
        g_part[kslice][row0 + r][1] = acc[1];
        g_part[kslice][row0 + r + 8][0] = acc[2];
        g_part[kslice][row0 + r + 8][1] = acc[3];
    }
}

// ---------------------------------------------------------------------------
// Kernel 5: reduce split-K partials: out = d ⊙ (Σ partials) + b2
// ---------------------------------------------------------------------------
__global__ __launch_bounds__(256) void k_reduce(const float* __restrict__ b2,
                                                float* __restrict__ out) {
    int m = blockIdx.x * 256 + threadIdx.x;
    float s0 = 0.f, s1 = 0.f;
#pragma unroll
    for (int s = 0; s < KSPLIT; ++s) {
        s0 += g_part[s][m][0];
        s1 += g_part[s][m][1];
    }
    float dd = g_d[m];
    out[m * 2 + 0] = dd * s0 + b2[0];
    out[m * 2 + 1] = dd * s1 + b2[1];
}

// ---------------------------------------------------------------------------
// Launch
// ---------------------------------------------------------------------------
extern "C" void kernel_launch(void* const* d_in, const int* in_sizes, int n_in,
                              void* d_out, int out_size) {
    const float *x = nullptr, *adj = nullptr, *W1 = nullptr, *b1 = nullptr,
                *W2 = nullptr, *b2 = nullptr;
    for (int i = 0; i < n_in; ++i) {
        switch (in_sizes[i]) {
            case NN * FIN:    x   = (const float*)d_in[i]; break;
            case 67108864:    adj = (const float*)d_in[i]; break;
            case FIN * FHID:  W1  = (const float*)d_in[i]; break;
            case FHID:        b1  = (const float*)d_in[i]; break;
            case FHID * FOUT: W2  = (const float*)d_in[i]; break;
            case FOUT:        b2  = (const float*)d_in[i]; break;
            default: break;
        }
    }
    float* out = (float*)d_out;

    const int smem1 = ST * 64 * 72 * 2 * 2;            // 73728 B
    const int smem2 = ST * 64 * 72 * 2 + ST * 64 * 24 * 2;  // 49152 B
    cudaFuncSetAttribute(k_agg1, cudaFuncAttributeMaxDynamicSharedMemorySize, smem1);
    cudaFuncSetAttribute(k_agg2, cudaFuncAttributeMaxDynamicSharedMemorySize, smem2);

    k_rowsum_convert<<<NN, 256>>>(adj);
    k_xw1<<<NN / 16, 256>>>(x, W1);
    k_agg1<<<NN / 64, 256, smem1>>>(b1, W2);
    k_agg2<<<dim3(NN / 64, KSPLIT), 128, smem2>>>();
    k_reduce<<<NN / 256, 256>>>(b2, out);
}

// round 3
// speedup vs baseline: 1.9344x; 1.0582x over previous
#include <cuda_runtime.h>
#include <cuda_bf16.h>
#include <cstdint>

// ---------------------------------------------------------------------------
// Problem constants (fixed shapes)
// ---------------------------------------------------------------------------
#define NN   8192
#define FIN  128
#define FHID 64
#define FOUT 2
#define KSPLIT 4      // layer-2 aggregation split
#define KSPLIT1 2     // layer-1 aggregation split

// ---------------------------------------------------------------------------
// Scratch (__device__ globals -- sanctioned, no runtime allocs)
// ---------------------------------------------------------------------------
__device__ __nv_bfloat16 g_adjb[(size_t)NN * NN];     // 128 MB bf16 adjacency
__device__ float         g_d[NN];                      // d_inv_sqrt
__device__ __nv_bfloat16 g_z1[NN * FHID];              // d ⊙ (x@W1)  [8192,64]
__device__ __nv_bfloat16 g_z2[NN * 8];                 // d ⊙ (h@W2)  [8192,8]
__device__ float         g_part1[KSPLIT1][NN][FHID];   // layer-1 split-K partials (4 MB)
__device__ float         g_part[KSPLIT][NN][2];        // layer-2 split-K partials

// ---------------------------------------------------------------------------
// PTX helpers
// ---------------------------------------------------------------------------
__device__ __forceinline__ unsigned smem_u32(const void* p) {
    return (unsigned)__cvta_generic_to_shared(p);
}
__device__ __forceinline__ void cp16(void* dst, const void* src) {
    unsigned d = smem_u32(dst);
    asm volatile("cp.async.cg.shared.global [%0],[%1],16;\n" :: "r"(d), "l"(src));
}
__device__ __forceinline__ void cp_commit() {
    asm volatile("cp.async.commit_group;\n");
}
__device__ __forceinline__ void cp_wait_2() {
    asm volatile("cp.async.wait_group 2;\n");
}
__device__ __forceinline__ void ldmatrix_x4(uint32_t& a0, uint32_t& a1, uint32_t& a2, uint32_t& a3,
                                            unsigned addr) {
    asm volatile("ldmatrix.sync.aligned.m8n8.x4.shared.b16 {%0,%1,%2,%3},[%4];\n"
                 : "=r"(a0), "=r"(a1), "=r"(a2), "=r"(a3) : "r"(addr));
}
__device__ __forceinline__ void ldmatrix_x2_trans(uint32_t& b0, uint32_t& b1, unsigned addr) {
    asm volatile("ldmatrix.sync.aligned.m8n8.x2.trans.shared.b16 {%0,%1},[%2];\n"
                 : "=r"(b0), "=r"(b1) : "r"(addr));
}
__device__ __forceinline__ void mma_bf16(float c[4],
                                         uint32_t a0, uint32_t a1, uint32_t a2, uint32_t a3,
                                         uint32_t b0, uint32_t b1) {
    asm volatile("mma.sync.aligned.m16n8k16.row.col.f32.bf16.bf16.f32 "
                 "{%0,%1,%2,%3},{%4,%5,%6,%7},{%8,%9},{%0,%1,%2,%3};\n"
                 : "+f"(c[0]), "+f"(c[1]), "+f"(c[2]), "+f"(c[3])
                 : "r"(a0), "r"(a1), "r"(a2), "r"(a3), "r"(b0), "r"(b1));
}
__device__ __forceinline__ unsigned bf2_bits(__nv_bfloat162 v) {
    return *reinterpret_cast<unsigned*>(&v);
}

// ---------------------------------------------------------------------------
// Kernel 1: row sums of adj (fp32) + convert adj -> bf16 scratch.
// One block per row; each thread: 4 iters of (2 float4 loads -> 1 uint4 store).
// ---------------------------------------------------------------------------
__global__ __launch_bounds__(256) void k_rowsum_convert(const float* __restrict__ adj) {
    int row = blockIdx.x;
    const float4* src = reinterpret_cast<const float4*>(adj + (size_t)row * NN);
    uint4* dst = reinterpret_cast<uint4*>(g_adjb + (size_t)row * NN);
    float s = 0.f;
#pragma unroll
    for (int it = 0; it < 4; ++it) {
        int idx = it * 512 + threadIdx.x * 2;     // float4 index
        float4 v0 = __ldcs(src + idx);
        float4 v1 = __ldcs(src + idx + 1);
        s += ((v0.x + v0.y) + (v0.z + v0.w)) + ((v1.x + v1.y) + (v1.z + v1.w));
        uint4 o;
        o.x = bf2_bits(__floats2bfloat162_rn(v0.x, v0.y));
        o.y = bf2_bits(__floats2bfloat162_rn(v0.z, v0.w));
        o.z = bf2_bits(__floats2bfloat162_rn(v1.x, v1.y));
        o.w = bf2_bits(__floats2bfloat162_rn(v1.z, v1.w));
        dst[idx >> 1] = o;
    }
    for (int o = 16; o; o >>= 1) s += __shfl_xor_sync(0xFFFFFFFFu, s, o);
    __shared__ float ws[8];
    if ((threadIdx.x & 31) == 0) ws[threadIdx.x >> 5] = s;
    __syncthreads();
    if (threadIdx.x == 0) {
        float t = 0.f;
#pragma unroll
        for (int w = 0; w < 8; ++w) t += ws[w];
        g_d[row] = rsqrtf(t + 1e-6f);
    }
}

// ---------------------------------------------------------------------------
// Kernel 2: z1 = bf16( d ⊙ (x @ W1) ).
// ---------------------------------------------------------------------------
__global__ __launch_bounds__(256) void k_xw1(const float* __restrict__ x,
                                             const float* __restrict__ W1) {
    __shared__ float W1s[FIN][FHID];
    __shared__ float xs[16][FIN];
    int tid = threadIdx.x;
    int r0 = blockIdx.x * 16;
    for (int i = tid; i < FIN * FHID; i += 256) W1s[i >> 6][i & 63] = W1[i];
    for (int i = tid; i < 16 * FIN; i += 256) xs[i >> 7][i & 127] = x[(size_t)r0 * FIN + i];
    __syncthreads();
    int f = tid & 63;
    int rb = tid >> 6;
    float acc[4] = {0.f, 0.f, 0.f, 0.f};
#pragma unroll
    for (int k = 0; k < FIN; ++k) {
        float w = W1s[k][f];
#pragma unroll
        for (int j = 0; j < 4; ++j) acc[j] += xs[rb + j * 4][k] * w;
    }
#pragma unroll
    for (int j = 0; j < 4; ++j) {
        int row = r0 + rb + j * 4;
        g_z1[row * FHID + f] = __float2bfloat16(g_d[row] * acc[j]);
    }
}

// ---------------------------------------------------------------------------
// Kernel 3: agg1 split-K: g_part1[ksl] = adjb[:, kslice] @ z1[kslice, :]
// CTA tile 64x64, K_TILE=64, 4-stage pipeline, single barrier per iteration.
// ---------------------------------------------------------------------------
#define KT 64
#define ST 4

__global__ __launch_bounds__(256) void k_agg1() {
    extern __shared__ __align__(16) unsigned char dyn[];
    __nv_bfloat16* Abuf = reinterpret_cast<__nv_bfloat16*>(dyn);     // [ST][64][72]
    __nv_bfloat16* Bbuf = Abuf + ST * 64 * 72;                        // [ST][64][72]

    int tid = threadIdx.x;
    int warp = tid >> 5, lane = tid & 31;
    int wm = warp >> 2, wn = warp & 3;
    int row0 = blockIdx.x * 64;
    int ksl = blockIdx.y;
    int kbase = ksl * (NN / KSPLIT1);    // 4096
    float acc[2][2][4] = {};
    const __nv_bfloat16* Ag = g_adjb + (size_t)row0 * NN;

    auto load_tiles = [&](int s, int k0) {
        __nv_bfloat16* As = Abuf + s * 64 * 72;
        __nv_bfloat16* Bs = Bbuf + s * 64 * 72;
#pragma unroll
        for (int i = 0; i < 2; ++i) {
            int c = tid + i * 256;
            int r = c >> 3, col = (c & 7) * 8;
            cp16(As + r * 72 + col, Ag + (size_t)r * NN + k0 + col);
            cp16(Bs + r * 72 + col, g_z1 + (size_t)(k0 + r) * FHID + col);
        }
    };

#pragma unroll
    for (int s = 0; s < ST - 1; ++s) { load_tiles(s, kbase + s * KT); cp_commit(); }

    const int NIT = (NN / KSPLIT1) / KT;   // 64
    for (int it = 0; it < NIT; ++it) {
        cp_wait_2();
        __syncthreads();
        if (it + ST - 1 < NIT) load_tiles((it + ST - 1) & (ST - 1), kbase + (it + ST - 1) * KT);
        cp_commit();
        int s = it & (ST - 1);
        __nv_bfloat16* As = Abuf + s * 64 * 72;
        __nv_bfloat16* Bs = Bbuf + s * 64 * 72;
#pragma unroll
        for (int ks = 0; ks < 4; ++ks) {
            uint32_t a[2][4], b[2][2];
#pragma unroll
            for (int mt = 0; mt < 2; ++mt) {
                unsigned ad = smem_u32(As + (wm * 32 + mt * 16 + (lane & 15)) * 72
                                          + ks * 16 + (lane >> 4) * 8);
                ldmatrix_x4(a[mt][0], a[mt][1], a[mt][2], a[mt][3], ad);
            }
#pragma unroll
            for (int nt = 0; nt < 2; ++nt) {
                unsigned bd = smem_u32(Bs + (ks * 16 + (lane & 15)) * 72 + wn * 16 + nt * 8);
                ldmatrix_x2_trans(b[nt][0], b[nt][1], bd);
            }
#pragma unroll
            for (int mt = 0; mt < 2; ++mt)
#pragma unroll
                for (int nt = 0; nt < 2; ++nt)
                    mma_bf16(acc[mt][nt], a[mt][0], a[mt][1], a[mt][2], a[mt][3],
                             b[nt][0], b[nt][1]);
        }
    }

    // write fp32 partials (two consecutive floats per fragment pair -> STG.64)
#pragma unroll
    for (int mt = 0; mt < 2; ++mt) {
#pragma unroll
        for (int nt = 0; nt < 2; ++nt) {
            int cbase = wn * 16 + nt * 8 + (lane & 3) * 2;
#pragma unroll
            for (int half = 0; half < 2; ++half) {
                int r = wm * 32 + mt * 16 + (lane >> 2) + half * 8;
                float2 v = make_float2(acc[mt][nt][half * 2 + 0], acc[mt][nt][half * 2 + 1]);
                *reinterpret_cast<float2*>(&g_part1[ksl][row0 + r][cbase]) = v;
            }
        }
    }
}

// ---------------------------------------------------------------------------
// Kernel 3b: mid epilogue.  h = relu(d*(U0+U1)+b1); z2 = bf16(d ⊙ (h@W2)).
// One warp per row; lane covers cols {lane, lane+32}.
// ---------------------------------------------------------------------------
__global__ __launch_bounds__(256) void k_mid(const float* __restrict__ b1,
                                             const float* __restrict__ W2) {
    int warp = threadIdx.x >> 5, lane = threadIdx.x & 31;
    int row = blockIdx.x * 8 + warp;
    float dd = g_d[row];
    float s0 = 0.f, s1 = 0.f;
#pragma unroll
    for (int j = 0; j < 2; ++j) {
        int c = lane + j * 32;
        float u = g_part1[0][row][c] + g_part1[1][row][c];
        float h = fmaxf(dd * u + b1[c], 0.f);
        s0 += h * W2[c * 2 + 0];
        s1 += h * W2[c * 2 + 1];
    }
    for (int o = 16; o; o >>= 1) {
        s0 += __shfl_xor_sync(0xFFFFFFFFu, s0, o);
        s1 += __shfl_xor_sync(0xFFFFFFFFu, s1, o);
    }
    if (lane == 0) {
        uint4 o;
        o.x = bf2_bits(__floats2bfloat162_rn(dd * s0, dd * s1));
        o.y = 0u; o.z = 0u; o.w = 0u;
        *reinterpret_cast<uint4*>(&g_z2[(size_t)row * 8]) = o;
    }
}

// ---------------------------------------------------------------------------
// Kernel 4: agg2 split-K: g_part[ksl] = adjb[:, kslice] @ z2[kslice, :]
// M_TILE=64, K range 2048 per slice, 4-stage pipeline, single barrier.
// ---------------------------------------------------------------------------
__global__ __launch_bounds__(128) void k_agg2() {
    extern __shared__ __align__(16) unsigned char dyn[];
    __nv_bfloat16* Abuf = reinterpret_cast<__nv_bfloat16*>(dyn);   // [ST][64][72]
    __nv_bfloat16* Bbuf = Abuf + ST * 64 * 72;                      // [ST][64][24]

    int tid = threadIdx.x, warp = tid >> 5, lane = tid & 31;
    int row0 = blockIdx.x * 64;
    int kslice = blockIdx.y;
    int kbase = kslice * (NN / KSPLIT);   // 2048
    float acc[4] = {0.f, 0.f, 0.f, 0.f};
    const __nv_bfloat16* Ag = g_adjb + (size_t)row0 * NN;

    auto load_tiles = [&](int s, int k0) {
        __nv_bfloat16* As = Abuf + s * 64 * 72;
        __nv_bfloat16* Bs = Bbuf + s * 64 * 24;
#pragma unroll
        for (int i = 0; i < 4; ++i) {
            int c = tid + i * 128;
            int r = c >> 3, col = (c & 7) * 8;
            cp16(As + r * 72 + col, Ag + (size_t)r * NN + k0 + col);
        }
        if (tid < 64) cp16(Bs + tid * 24, g_z2 + (size_t)(k0 + tid) * 8);
    };

#pragma unroll
    for (int s = 0; s < ST - 1; ++s) { load_tiles(s, kbase + s * KT); cp_commit(); }

    const int NIT = (NN / KSPLIT) / KT;   // 32
    for (int it = 0; it < NIT; ++it) {
        cp_wait_2();
        __syncthreads();
        if (it + ST - 1 < NIT) load_tiles((it + ST - 1) & (ST - 1), kbase + (it + ST - 1) * KT);
        cp_commit();
        int s = it & (ST - 1);
        __nv_bfloat16* As = Abuf + s * 64 * 72;
        __nv_bfloat16* Bs = Bbuf + s * 64 * 24;
#pragma unroll
        for (int ks = 0; ks < 4; ++ks) {
            uint32_t a0, a1, a2, a3, b0, b1r;
            unsigned ad = smem_u32(As + (warp * 16 + (lane & 15)) * 72
                                      + ks * 16 + (lane >> 4) * 8);
            ldmatrix_x4(a0, a1, a2, a3, ad);
            unsigned bd = smem_u32(Bs + (ks * 16 + (lane & 15)) * 24);
            ldmatrix_x2_trans(b0, b1r, bd);
            mma_bf16(acc, a0, a1, a2, a3, b0, b1r);
        }
    }

    if ((lane & 3) == 0) {
        int r = warp * 16 + (lane >> 2);
        g_part[kslice][row0 + r][0] = acc[0];
        g_part[kslice][row0 + r][1] = acc[1];
        g_part[kslice][row0 + r + 8][0] = acc[2];
        g_part[kslice][row0 + r + 8][1] = acc[3];
    }
}

// ---------------------------------------------------------------------------
// Kernel 5: reduce split-K partials: out = d ⊙ (Σ partials) + b2
// ---------------------------------------------------------------------------
__global__ __launch_bounds__(256) void k_reduce(const float* __restrict__ b2,
                                                float* __restrict__ out) {
    int m = blockIdx.x * 256 + threadIdx.x;
    float s0 = 0.f, s1 = 0.f;
#pragma unroll
    for (int s = 0; s < KSPLIT; ++s) {
        s0 += g_part[s][m][0];
        s1 += g_part[s][m][1];
    }
    float dd = g_d[m];
    out[m * 2 + 0] = dd * s0 + b2[0];
    out[m * 2 + 1] = dd * s1 + b2[1];
}

// ---------------------------------------------------------------------------
// Launch
// ---------------------------------------------------------------------------
extern "C" void kernel_launch(void* const* d_in, const int* in_sizes, int n_in,
                              void* d_out, int out_size) {
    const float *x = nullptr, *adj = nullptr, *W1 = nullptr, *b1 = nullptr,
                *W2 = nullptr, *b2 = nullptr;
    for (int i = 0; i < n_in; ++i) {
        switch (in_sizes[i]) {
            case NN * FIN:    x   = (const float*)d_in[i]; break;
            case 67108864:    adj = (const float*)d_in[i]; break;
            case FIN * FHID:  W1  = (const float*)d_in[i]; break;
            case FHID:        b1  = (const float*)d_in[i]; break;
            case FHID * FOUT: W2  = (const float*)d_in[i]; break;
            case FOUT:        b2  = (const float*)d_in[i]; break;
            default: break;
        }
    }
    float* out = (float*)d_out;

    const int smem1 = ST * 64 * 72 * 2 * 2;                 // 73728 B
    const int smem2 = ST * 64 * 72 * 2 + ST * 64 * 24 * 2;  // 49152 B
    cudaFuncSetAttribute(k_agg1, cudaFuncAttributeMaxDynamicSharedMemorySize, smem1);
    cudaFuncSetAttribute(k_agg2, cudaFuncAttributeMaxDynamicSharedMemorySize, smem2);

    k_rowsum_convert<<<NN, 256>>>(adj);
    k_xw1<<<NN / 16, 256>>>(x, W1);
    k_agg1<<<dim3(NN / 64, KSPLIT1), 256, smem1>>>();
    k_mid<<<NN / 8, 256>>>(b1, W2);
    k_agg2<<<dim3(NN / 64, KSPLIT), 128, smem2>>>();
    k_reduce<<<NN / 256, 256>>>(b2, out);
}

// round 4
// speedup vs baseline: 1.9348x; 1.0002x over previous
#include <cuda_runtime.h>
#include <cuda_bf16.h>
#include <cstdint>

// ---------------------------------------------------------------------------
// Problem constants (fixed shapes)
// ---------------------------------------------------------------------------
#define NN   8192
#define FIN  128
#define FHID 64
#define FOUT 2
#define KSPLIT  8     // layer-2 aggregation split
#define KSPLIT1 4     // layer-1 aggregation split

// ---------------------------------------------------------------------------
// Scratch (__device__ globals -- sanctioned, no runtime allocs)
// ---------------------------------------------------------------------------
__device__ __nv_bfloat16 g_adjb[(size_t)NN * NN];     // 128 MB bf16 adjacency
__device__ float         g_d[NN];                      // d_inv_sqrt
__device__ __nv_bfloat16 g_z1[NN * FHID];              // d ⊙ (x@W1)  [8192,64]
__device__ __nv_bfloat16 g_z2[NN * 8];                 // d ⊙ (h@W2)  [8192,8]
__device__ float         g_part1[KSPLIT1][NN][FHID];   // layer-1 split-K partials (8 MB)
__device__ float         g_part[KSPLIT][NN][2];        // layer-2 split-K partials

// ---------------------------------------------------------------------------
// PTX helpers
// ---------------------------------------------------------------------------
__device__ __forceinline__ unsigned smem_u32(const void* p) {
    return (unsigned)__cvta_generic_to_shared(p);
}
__device__ __forceinline__ void cp16(void* dst, const void* src) {
    unsigned d = smem_u32(dst);
    asm volatile("cp.async.cg.shared.global [%0],[%1],16;\n" :: "r"(d), "l"(src));
}
__device__ __forceinline__ void cp_commit() {
    asm volatile("cp.async.commit_group;\n");
}
__device__ __forceinline__ void cp_wait_2() {
    asm volatile("cp.async.wait_group 2;\n");
}
__device__ __forceinline__ void ldmatrix_x4(uint32_t& a0, uint32_t& a1, uint32_t& a2, uint32_t& a3,
                                            unsigned addr) {
    asm volatile("ldmatrix.sync.aligned.m8n8.x4.shared.b16 {%0,%1,%2,%3},[%4];\n"
                 : "=r"(a0), "=r"(a1), "=r"(a2), "=r"(a3) : "r"(addr));
}
__device__ __forceinline__ void ldmatrix_x2_trans(uint32_t& b0, uint32_t& b1, unsigned addr) {
    asm volatile("ldmatrix.sync.aligned.m8n8.x2.trans.shared.b16 {%0,%1},[%2];\n"
                 : "=r"(b0), "=r"(b1) : "r"(addr));
}
__device__ __forceinline__ void mma_bf16(float c[4],
                                         uint32_t a0, uint32_t a1, uint32_t a2, uint32_t a3,
                                         uint32_t b0, uint32_t b1) {
    asm volatile("mma.sync.aligned.m16n8k16.row.col.f32.bf16.bf16.f32 "
                 "{%0,%1,%2,%3},{%4,%5,%6,%7},{%8,%9},{%0,%1,%2,%3};\n"
                 : "+f"(c[0]), "+f"(c[1]), "+f"(c[2]), "+f"(c[3])
                 : "r"(a0), "r"(a1), "r"(a2), "r"(a3), "r"(b0), "r"(b1));
}
__device__ __forceinline__ unsigned bf2_bits(__nv_bfloat162 v) {
    return *reinterpret_cast<unsigned*>(&v);
}

// ---------------------------------------------------------------------------
// Kernel 1: row sums of adj (fp32) + convert adj -> bf16 scratch.
// ---------------------------------------------------------------------------
__global__ __launch_bounds__(256) void k_rowsum_convert(const float* __restrict__ adj) {
    int row = blockIdx.x;
    const float4* src = reinterpret_cast<const float4*>(adj + (size_t)row * NN);
    uint4* dst = reinterpret_cast<uint4*>(g_adjb + (size_t)row * NN);
    float s = 0.f;
#pragma unroll
    for (int it = 0; it < 4; ++it) {
        int idx = it * 512 + threadIdx.x * 2;
        float4 v0 = __ldcs(src + idx);
        float4 v1 = __ldcs(src + idx + 1);
        s += ((v0.x + v0.y) + (v0.z + v0.w)) + ((v1.x + v1.y) + (v1.z + v1.w));
        uint4 o;
        o.x = bf2_bits(__floats2bfloat162_rn(v0.x, v0.y));
        o.y = bf2_bits(__floats2bfloat162_rn(v0.z, v0.w));
        o.z = bf2_bits(__floats2bfloat162_rn(v1.x, v1.y));
        o.w = bf2_bits(__floats2bfloat162_rn(v1.z, v1.w));
        dst[idx >> 1] = o;
    }
    for (int o = 16; o; o >>= 1) s += __shfl_xor_sync(0xFFFFFFFFu, s, o);
    __shared__ float ws[8];
    if ((threadIdx.x & 31) == 0) ws[threadIdx.x >> 5] = s;
    __syncthreads();
    if (threadIdx.x == 0) {
        float t = 0.f;
#pragma unroll
        for (int w = 0; w < 8; ++w) t += ws[w];
        g_d[row] = rsqrtf(t + 1e-6f);
    }
}

// ---------------------------------------------------------------------------
// Kernel 2: z1 = bf16( d ⊙ (x @ W1) ).
// ---------------------------------------------------------------------------
__global__ __launch_bounds__(256) void k_xw1(const float* __restrict__ x,
                                             const float* __restrict__ W1) {
    __shared__ float W1s[FIN][FHID];
    __shared__ float xs[16][FIN];
    int tid = threadIdx.x;
    int r0 = blockIdx.x * 16;
    for (int i = tid; i < FIN * FHID; i += 256) W1s[i >> 6][i & 63] = W1[i];
    for (int i = tid; i < 16 * FIN; i += 256) xs[i >> 7][i & 127] = x[(size_t)r0 * FIN + i];
    __syncthreads();
    int f = tid & 63;
    int rb = tid >> 6;
    float acc[4] = {0.f, 0.f, 0.f, 0.f};
#pragma unroll
    for (int k = 0; k < FIN; ++k) {
        float w = W1s[k][f];
#pragma unroll
        for (int j = 0; j < 4; ++j) acc[j] += xs[rb + j * 4][k] * w;
    }
#pragma unroll
    for (int j = 0; j < 4; ++j) {
        int row = r0 + rb + j * 4;
        g_z1[row * FHID + f] = __float2bfloat16(g_d[row] * acc[j]);
    }
}

// ---------------------------------------------------------------------------
// Kernel 3: agg1 split-K: g_part1[ksl] = adjb[:, kslice] @ z1[kslice, :]
// CTA tile 64x64, K_TILE=64, 4-stage pipeline, single barrier per iteration.
// ---------------------------------------------------------------------------
#define KT 64
#define ST 4

__global__ __launch_bounds__(256) void k_agg1() {
    extern __shared__ __align__(16) unsigned char dyn[];
    __nv_bfloat16* Abuf = reinterpret_cast<__nv_bfloat16*>(dyn);     // [ST][64][72]
    __nv_bfloat16* Bbuf = Abuf + ST * 64 * 72;                        // [ST][64][72]

    int tid = threadIdx.x;
    int warp = tid >> 5, lane = tid & 31;
    int wm = warp >> 2, wn = warp & 3;
    int row0 = blockIdx.x * 64;
    int ksl = blockIdx.y;
    int kbase = ksl * (NN / KSPLIT1);    // 2048
    float acc[2][2][4] = {};
    const __nv_bfloat16* Ag = g_adjb + (size_t)row0 * NN;

    auto load_tiles = [&](int s, int k0) {
        __nv_bfloat16* As = Abuf + s * 64 * 72;
        __nv_bfloat16* Bs = Bbuf + s * 64 * 72;
#pragma unroll
        for (int i = 0; i < 2; ++i) {
            int c = tid + i * 256;
            int r = c >> 3, col = (c & 7) * 8;
            cp16(As + r * 72 + col, Ag + (size_t)r * NN + k0 + col);
            cp16(Bs + r * 72 + col, g_z1 + (size_t)(k0 + r) * FHID + col);
        }
    };

#pragma unroll
    for (int s = 0; s < ST - 1; ++s) { load_tiles(s, kbase + s * KT); cp_commit(); }

    const int NIT = (NN / KSPLIT1) / KT;   // 32
    for (int it = 0; it < NIT; ++it) {
        cp_wait_2();
        __syncthreads();
        if (it + ST - 1 < NIT) load_tiles((it + ST - 1) & (ST - 1), kbase + (it + ST - 1) * KT);
        cp_commit();
        int s = it & (ST - 1);
        __nv_bfloat16* As = Abuf + s * 64 * 72;
        __nv_bfloat16* Bs = Bbuf + s * 64 * 72;
#pragma unroll
        for (int ks = 0; ks < 4; ++ks) {
            uint32_t a[2][4], b[2][2];
#pragma unroll
            for (int mt = 0; mt < 2; ++mt) {
                unsigned ad = smem_u32(As + (wm * 32 + mt * 16 + (lane & 15)) * 72
                                          + ks * 16 + (lane >> 4) * 8);
                ldmatrix_x4(a[mt][0], a[mt][1], a[mt][2], a[mt][3], ad);
            }
#pragma unroll
            for (int nt = 0; nt < 2; ++nt) {
                unsigned bd = smem_u32(Bs + (ks * 16 + (lane & 15)) * 72 + wn * 16 + nt * 8);
                ldmatrix_x2_trans(b[nt][0], b[nt][1], bd);
            }
#pragma unroll
            for (int mt = 0; mt < 2; ++mt)
#pragma unroll
                for (int nt = 0; nt < 2; ++nt)
                    mma_bf16(acc[mt][nt], a[mt][0], a[mt][1], a[mt][2], a[mt][3],
                             b[nt][0], b[nt][1]);
        }
    }

#pragma unroll
    for (int mt = 0; mt < 2; ++mt) {
#pragma unroll
        for (int nt = 0; nt < 2; ++nt) {
            int cbase = wn * 16 + nt * 8 + (lane & 3) * 2;
#pragma unroll
            for (int half = 0; half < 2; ++half) {
                int r = wm * 32 + mt * 16 + (lane >> 2) + half * 8;
                float2 v = make_float2(acc[mt][nt][half * 2 + 0], acc[mt][nt][half * 2 + 1]);
                *reinterpret_cast<float2*>(&g_part1[ksl][row0 + r][cbase]) = v;
            }
        }
    }
}

// ---------------------------------------------------------------------------
// Kernel 3b: mid epilogue.  h = relu(d*ΣU+b1); z2 = bf16(d ⊙ (h@W2)).
// One warp per row; lane covers cols {lane, lane+32}.
// ---------------------------------------------------------------------------
__global__ __launch_bounds__(256) void k_mid(const float* __restrict__ b1,
                                             const float* __restrict__ W2) {
    int warp = threadIdx.x >> 5, lane = threadIdx.x & 31;
    int row = blockIdx.x * 8 + warp;
    float dd = g_d[row];
    float s0 = 0.f, s1 = 0.f;
#pragma unroll
    for (int j = 0; j < 2; ++j) {
        int c = lane + j * 32;
        float u = 0.f;
#pragma unroll
        for (int s = 0; s < KSPLIT1; ++s) u += g_part1[s][row][c];
        float h = fmaxf(dd * u + b1[c], 0.f);
        s0 += h * W2[c * 2 + 0];
        s1 += h * W2[c * 2 + 1];
    }
    for (int o = 16; o; o >>= 1) {
        s0 += __shfl_xor_sync(0xFFFFFFFFu, s0, o);
        s1 += __shfl_xor_sync(0xFFFFFFFFu, s1, o);
    }
    if (lane == 0) {
        uint4 o;
        o.x = bf2_bits(__floats2bfloat162_rn(dd * s0, dd * s1));
        o.y = 0u; o.z = 0u; o.w = 0u;
        *reinterpret_cast<uint4*>(&g_z2[(size_t)row * 8]) = o;
    }
}

// ---------------------------------------------------------------------------
// Kernel 4: agg2 split-K: g_part[ksl] = adjb[:, kslice] @ z2[kslice, :]
// M_TILE=64, K range 1024 per slice, 4-stage pipeline, single barrier.
// ---------------------------------------------------------------------------
__global__ __launch_bounds__(128) void k_agg2() {
    extern __shared__ __align__(16) unsigned char dyn[];
    __nv_bfloat16* Abuf = reinterpret_cast<__nv_bfloat16*>(dyn);   // [ST][64][72]
    __nv_bfloat16* Bbuf = Abuf + ST * 64 * 72;                      // [ST][64][24]

    int tid = threadIdx.x, warp = tid >> 5, lane = tid & 31;
    int row0 = blockIdx.x * 64;
    int kslice = blockIdx.y;
    int kbase = kslice * (NN / KSPLIT);   // 1024
    float acc[4] = {0.f, 0.f, 0.f, 0.f};
    const __nv_bfloat16* Ag = g_adjb + (size_t)row0 * NN;

    auto load_tiles = [&](int s, int k0) {
        __nv_bfloat16* As = Abuf + s * 64 * 72;
        __nv_bfloat16* Bs = Bbuf + s * 64 * 24;
#pragma unroll
        for (int i = 0; i < 4; ++i) {
            int c = tid + i * 128;
            int r = c >> 3, col = (c & 7) * 8;
            cp16(As + r * 72 + col, Ag + (size_t)r * NN + k0 + col);
        }
        if (tid < 64) cp16(Bs + tid * 24, g_z2 + (size_t)(k0 + tid) * 8);
    };

#pragma unroll
    for (int s = 0; s < ST - 1; ++s) { load_tiles(s, kbase + s * KT); cp_commit(); }

    const int NIT = (NN / KSPLIT) / KT;   // 16
    for (int it = 0; it < NIT; ++it) {
        cp_wait_2();
        __syncthreads();
        if (it + ST - 1 < NIT) load_tiles((it + ST - 1) & (ST - 1), kbase + (it + ST - 1) * KT);
        cp_commit();
        int s = it & (ST - 1);
        __nv_bfloat16* As = Abuf + s * 64 * 72;
        __nv_bfloat16* Bs = Bbuf + s * 64 * 24;
#pragma unroll
        for (int ks = 0; ks < 4; ++ks) {
            uint32_t a0, a1, a2, a3, b0, b1r;
            unsigned ad = smem_u32(As + (warp * 16 + (lane & 15)) * 72
                                      + ks * 16 + (lane >> 4) * 8);
            ldmatrix_x4(a0, a1, a2, a3, ad);
            unsigned bd = smem_u32(Bs + (ks * 16 + (lane & 15)) * 24);
            ldmatrix_x2_trans(b0, b1r, bd);
            mma_bf16(acc, a0, a1, a2, a3, b0, b1r);
        }
    }

    if ((lane & 3) == 0) {
        int r = warp * 16 + (lane >> 2);
        g_part[kslice][row0 + r][0] = acc[0];
        g_part[kslice][row0 + r][1] = acc[1];
        g_part[kslice][row0 + r + 8][0] = acc[2];
        g_part[kslice][row0 + r + 8][1] = acc[3];
    }
}

// ---------------------------------------------------------------------------
// Kernel 5: reduce split-K partials: out = d ⊙ (Σ partials) + b2
// ---------------------------------------------------------------------------
__global__ __launch_bounds__(256) void k_reduce(const float* __restrict__ b2,
                                                float* __restrict__ out) {
    int m = blockIdx.x * 256 + threadIdx.x;
    float s0 = 0.f, s1 = 0.f;
#pragma unroll
    for (int s = 0; s < KSPLIT; ++s) {
        s0 += g_part[s][m][0];
        s1 += g_part[s][m][1];
    }
    float dd = g_d[m];
    out[m * 2 + 0] = dd * s0 + b2[0];
    out[m * 2 + 1] = dd * s1 + b2[1];
}

// ---------------------------------------------------------------------------
// Launch
// ---------------------------------------------------------------------------
extern "C" void kernel_launch(void* const* d_in, const int* in_sizes, int n_in,
                              void* d_out, int out_size) {
    const float *x = nullptr, *adj = nullptr, *W1 = nullptr, *b1 = nullptr,
                *W2 = nullptr, *b2 = nullptr;
    for (int i = 0; i < n_in; ++i) {
        switch (in_sizes[i]) {
            case NN * FIN:    x   = (const float*)d_in[i]; break;
            case 67108864:    adj = (const float*)d_in[i]; break;
            case FIN * FHID:  W1  = (const float*)d_in[i]; break;
            case FHID:        b1  = (const float*)d_in[i]; break;
            case FHID * FOUT: W2  = (const float*)d_in[i]; break;
            case FOUT:        b2  = (const float*)d_in[i]; break;
            default: break;
        }
    }
    float* out = (float*)d_out;

    const int smem1 = ST * 64 * 72 * 2 * 2;                 // 73728 B
    const int smem2 = ST * 64 * 72 * 2 + ST * 64 * 24 * 2;  // 49152 B
    cudaFuncSetAttribute(k_agg1, cudaFuncAttributeMaxDynamicSharedMemorySize, smem1);
    cudaFuncSetAttribute(k_agg2, cudaFuncAttributeMaxDynamicSharedMemorySize, smem2);

    k_rowsum_convert<<<NN, 256>>>(adj);
    k_xw1<<<NN / 16, 256>>>(x, W1);
    k_agg1<<<dim3(NN / 64, KSPLIT1), 256, smem1>>>();
    k_mid<<<NN / 8, 256>>>(b1, W2);
    k_agg2<<<dim3(NN / 64, KSPLIT), 128, smem2>>>();
    k_reduce<<<NN / 256, 256>>>(b2, out);
}

// round 5
// speedup vs baseline: 2.0600x; 1.0647x over previous
#include <cuda_runtime.h>
#include <cuda_bf16.h>
#include <cstdint>

// ---------------------------------------------------------------------------
// Problem constants (fixed shapes)
// ---------------------------------------------------------------------------
#define NN   8192
#define FIN  128
#define FHID 64
#define FOUT 2
#define KSPLIT  8     // layer-2 aggregation split
#define KSPLIT1 4     // layer-1 aggregation split

// ---------------------------------------------------------------------------
// Scratch (__device__ globals -- sanctioned, no runtime allocs)
// ---------------------------------------------------------------------------
__device__ __nv_bfloat16 g_adjb[(size_t)NN * NN];     // 128 MB bf16 adjacency
__device__ float         g_d[NN];                      // d_inv_sqrt
__device__ __nv_bfloat16 g_z1[NN * FHID];              // d ⊙ (x@W1)  [8192,64]
__device__ __nv_bfloat16 g_z2[NN * 8];                 // d ⊙ (h@W2)  [8192,8]
__device__ float         g_part1[KSPLIT1][NN][FHID];   // layer-1 split-K partials
__device__ float         g_part[KSPLIT][NN][2];        // layer-2 split-K partials

// ---------------------------------------------------------------------------
// PTX helpers
// ---------------------------------------------------------------------------
__device__ __forceinline__ unsigned smem_u32(const void* p) {
    return (unsigned)__cvta_generic_to_shared(p);
}
__device__ __forceinline__ void cp16(void* dst, const void* src) {
    unsigned d = smem_u32(dst);
    asm volatile("cp.async.cg.shared.global [%0],[%1],16;\n" :: "r"(d), "l"(src));
}
__device__ __forceinline__ void cp_commit() {
    asm volatile("cp.async.commit_group;\n");
}
__device__ __forceinline__ void cp_wait_2() {
    asm volatile("cp.async.wait_group 2;\n");
}
__device__ __forceinline__ void ldmatrix_x4(uint32_t& a0, uint32_t& a1, uint32_t& a2, uint32_t& a3,
                                            unsigned addr) {
    asm volatile("ldmatrix.sync.aligned.m8n8.x4.shared.b16 {%0,%1,%2,%3},[%4];\n"
                 : "=r"(a0), "=r"(a1), "=r"(a2), "=r"(a3) : "r"(addr));
}
__device__ __forceinline__ void ldmatrix_x2_trans(uint32_t& b0, uint32_t& b1, unsigned addr) {
    asm volatile("ldmatrix.sync.aligned.m8n8.x2.trans.shared.b16 {%0,%1},[%2];\n"
                 : "=r"(b0), "=r"(b1) : "r"(addr));
}
__device__ __forceinline__ void mma_bf16(float c[4],
                                         uint32_t a0, uint32_t a1, uint32_t a2, uint32_t a3,
                                         uint32_t b0, uint32_t b1) {
    asm volatile("mma.sync.aligned.m16n8k16.row.col.f32.bf16.bf16.f32 "
                 "{%0,%1,%2,%3},{%4,%5,%6,%7},{%8,%9},{%0,%1,%2,%3};\n"
                 : "+f"(c[0]), "+f"(c[1]), "+f"(c[2]), "+f"(c[3])
                 : "r"(a0), "r"(a1), "r"(a2), "r"(a3), "r"(b0), "r"(b1));
}
__device__ __forceinline__ unsigned bf2_bits(__nv_bfloat162 v) {
    return *reinterpret_cast<unsigned*>(&v);
}

// ---------------------------------------------------------------------------
// Kernel 1: row sums of adj (fp32) + convert adj -> bf16 scratch.
// ---------------------------------------------------------------------------
__global__ __launch_bounds__(256) void k_rowsum_convert(const float* __restrict__ adj) {
    int row = blockIdx.x;
    const float4* src = reinterpret_cast<const float4*>(adj + (size_t)row * NN);
    uint4* dst = reinterpret_cast<uint4*>(g_adjb + (size_t)row * NN);
    float s = 0.f;
#pragma unroll
    for (int it = 0; it < 4; ++it) {
        int idx = it * 512 + threadIdx.x * 2;
        float4 v0 = __ldcs(src + idx);
        float4 v1 = __ldcs(src + idx + 1);
        s += ((v0.x + v0.y) + (v0.z + v0.w)) + ((v1.x + v1.y) + (v1.z + v1.w));
        uint4 o;
        o.x = bf2_bits(__floats2bfloat162_rn(v0.x, v0.y));
        o.y = bf2_bits(__floats2bfloat162_rn(v0.z, v0.w));
        o.z = bf2_bits(__floats2bfloat162_rn(v1.x, v1.y));
        o.w = bf2_bits(__floats2bfloat162_rn(v1.z, v1.w));
        dst[idx >> 1] = o;
    }
    for (int o = 16; o; o >>= 1) s += __shfl_xor_sync(0xFFFFFFFFu, s, o);
    __shared__ float ws[8];
    if ((threadIdx.x & 31) == 0) ws[threadIdx.x >> 5] = s;
    __syncthreads();
    if (threadIdx.x == 0) {
        float t = 0.f;
#pragma unroll
        for (int w = 0; w < 8; ++w) t += ws[w];
        g_d[row] = rsqrtf(t + 1e-6f);
    }
}

// ---------------------------------------------------------------------------
// Kernel 2: z1 = bf16( d ⊙ (x @ W1) ).
// ---------------------------------------------------------------------------
__global__ __launch_bounds__(256) void k_xw1(const float* __restrict__ x,
                                             const float* __restrict__ W1) {
    __shared__ float W1s[FIN][FHID];
    __shared__ float xs[16][FIN];
    int tid = threadIdx.x;
    int r0 = blockIdx.x * 16;
    for (int i = tid; i < FIN * FHID; i += 256) W1s[i >> 6][i & 63] = W1[i];
    for (int i = tid; i < 16 * FIN; i += 256) xs[i >> 7][i & 127] = x[(size_t)r0 * FIN + i];
    __syncthreads();
    int f = tid & 63;
    int rb = tid >> 6;
    float acc[4] = {0.f, 0.f, 0.f, 0.f};
#pragma unroll
    for (int k = 0; k < FIN; ++k) {
        float w = W1s[k][f];
#pragma unroll
        for (int j = 0; j < 4; ++j) acc[j] += xs[rb + j * 4][k] * w;
    }
#pragma unroll
    for (int j = 0; j < 4; ++j) {
        int row = r0 + rb + j * 4;
        g_z1[row * FHID + f] = __float2bfloat16(g_d[row] * acc[j]);
    }
}

// ---------------------------------------------------------------------------
// Kernel 3: agg1 split-K: g_part1[ksl] = adjb[:, kslice] @ z1[kslice, :]
// CTA tile 128x64, K_TILE=64, 4-stage pipeline, 8 warps (4m x 2n),
// warp tile 32x32.  smem: A[4][128][72] + B[4][64][72] bf16 = 110.6 KB.
// ---------------------------------------------------------------------------
#define KT 64
#define ST 4
#define A1_STRIDE (128 * 72)
#define B1_STRIDE (64 * 72)

__global__ __launch_bounds__(256) void k_agg1() {
    extern __shared__ __align__(16) unsigned char dyn[];
    __nv_bfloat16* Abuf = reinterpret_cast<__nv_bfloat16*>(dyn);     // [ST][128][72]
    __nv_bfloat16* Bbuf = Abuf + ST * A1_STRIDE;                      // [ST][64][72]

    int tid = threadIdx.x;
    int warp = tid >> 5, lane = tid & 31;
    int wm = warp >> 1, wn = warp & 1;            // 4m x 2n warp grid
    int row0 = blockIdx.x * 128;
    int ksl = blockIdx.y;
    int kbase = ksl * (NN / KSPLIT1);             // 2048
    float acc[2][4][4] = {};
    const __nv_bfloat16* Ag = g_adjb + (size_t)row0 * NN;

    auto load_tiles = [&](int s, int k0) {
        __nv_bfloat16* As = Abuf + s * A1_STRIDE;
        __nv_bfloat16* Bs = Bbuf + s * B1_STRIDE;
#pragma unroll
        for (int i = 0; i < 4; ++i) {             // A: 128 rows x 128B = 1024 chunks
            int c = tid + i * 256;
            int r = c >> 3, col = (c & 7) * 8;
            cp16(As + r * 72 + col, Ag + (size_t)r * NN + k0 + col);
        }
#pragma unroll
        for (int i = 0; i < 2; ++i) {             // B: 64 rows x 128B = 512 chunks
            int c = tid + i * 256;
            int r = c >> 3, col = (c & 7) * 8;
            cp16(Bs + r * 72 + col, g_z1 + (size_t)(k0 + r) * FHID + col);
        }
    };

#pragma unroll
    for (int s = 0; s < ST - 1; ++s) { load_tiles(s, kbase + s * KT); cp_commit(); }

    const int NIT = (NN / KSPLIT1) / KT;   // 32
    for (int it = 0; it < NIT; ++it) {
        cp_wait_2();
        __syncthreads();
        if (it + ST - 1 < NIT) load_tiles((it + ST - 1) & (ST - 1), kbase + (it + ST - 1) * KT);
        cp_commit();
        int s = it & (ST - 1);
        __nv_bfloat16* As = Abuf + s * A1_STRIDE;
        __nv_bfloat16* Bs = Bbuf + s * B1_STRIDE;
#pragma unroll
        for (int ks = 0; ks < 4; ++ks) {
            uint32_t a[2][4], b[4][2];
#pragma unroll
            for (int mt = 0; mt < 2; ++mt) {
                unsigned ad = smem_u32(As + (wm * 32 + mt * 16 + (lane & 15)) * 72
                                          + ks * 16 + (lane >> 4) * 8);
                ldmatrix_x4(a[mt][0], a[mt][1], a[mt][2], a[mt][3], ad);
            }
#pragma unroll
            for (int nt = 0; nt < 4; ++nt) {
                unsigned bd = smem_u32(Bs + (ks * 16 + (lane & 15)) * 72 + wn * 32 + nt * 8);
                ldmatrix_x2_trans(b[nt][0], b[nt][1], bd);
            }
#pragma unroll
            for (int mt = 0; mt < 2; ++mt)
#pragma unroll
                for (int nt = 0; nt < 4; ++nt)
                    mma_bf16(acc[mt][nt], a[mt][0], a[mt][1], a[mt][2], a[mt][3],
                             b[nt][0], b[nt][1]);
        }
    }

    // write fp32 partials (STG.64 pairs)
#pragma unroll
    for (int mt = 0; mt < 2; ++mt) {
#pragma unroll
        for (int nt = 0; nt < 4; ++nt) {
            int cbase = wn * 32 + nt * 8 + (lane & 3) * 2;
#pragma unroll
            for (int half = 0; half < 2; ++half) {
                int r = wm * 32 + mt * 16 + (lane >> 2) + half * 8;
                float2 v = make_float2(acc[mt][nt][half * 2 + 0], acc[mt][nt][half * 2 + 1]);
                *reinterpret_cast<float2*>(&g_part1[ksl][row0 + r][cbase]) = v;
            }
        }
    }
}

// ---------------------------------------------------------------------------
// Kernel 3b: mid epilogue.  h = relu(d*ΣU+b1); z2 = bf16(d ⊙ (h@W2)).
// One warp per row; lane covers cols {lane, lane+32}.
// ---------------------------------------------------------------------------
__global__ __launch_bounds__(256) void k_mid(const float* __restrict__ b1,
                                             const float* __restrict__ W2) {
    int warp = threadIdx.x >> 5, lane = threadIdx.x & 31;
    int row = blockIdx.x * 8 + warp;
    float dd = g_d[row];
    float s0 = 0.f, s1 = 0.f;
#pragma unroll
    for (int j = 0; j < 2; ++j) {
        int c = lane + j * 32;
        float u = 0.f;
#pragma unroll
        for (int s = 0; s < KSPLIT1; ++s) u += g_part1[s][row][c];
        float h = fmaxf(dd * u + b1[c], 0.f);
        s0 += h * W2[c * 2 + 0];
        s1 += h * W2[c * 2 + 1];
    }
    for (int o = 16; o; o >>= 1) {
        s0 += __shfl_xor_sync(0xFFFFFFFFu, s0, o);
        s1 += __shfl_xor_sync(0xFFFFFFFFu, s1, o);
    }
    if (lane == 0) {
        uint4 o;
        o.x = bf2_bits(__floats2bfloat162_rn(dd * s0, dd * s1));
        o.y = 0u; o.z = 0u; o.w = 0u;
        *reinterpret_cast<uint4*>(&g_z2[(size_t)row * 8]) = o;
    }
}

// ---------------------------------------------------------------------------
// Kernel 4: agg2 split-K: g_part[ksl] = adjb[:, kslice] @ z2[kslice, :]
// M_TILE=64, K range 1024 per slice, 4-stage pipeline, single barrier.
// ---------------------------------------------------------------------------
__global__ __launch_bounds__(128) void k_agg2() {
    extern __shared__ __align__(16) unsigned char dyn[];
    __nv_bfloat16* Abuf = reinterpret_cast<__nv_bfloat16*>(dyn);   // [ST][64][72]
    __nv_bfloat16* Bbuf = Abuf + ST * 64 * 72;                      // [ST][64][24]

    int tid = threadIdx.x, warp = tid >> 5, lane = tid & 31;
    int row0 = blockIdx.x * 64;
    int kslice = blockIdx.y;
    int kbase = kslice * (NN / KSPLIT);   // 1024
    float acc[4] = {0.f, 0.f, 0.f, 0.f};
    const __nv_bfloat16* Ag = g_adjb + (size_t)row0 * NN;

    auto load_tiles = [&](int s, int k0) {
        __nv_bfloat16* As = Abuf + s * 64 * 72;
        __nv_bfloat16* Bs = Bbuf + s * 64 * 24;
#pragma unroll
        for (int i = 0; i < 4; ++i) {
            int c = tid + i * 128;
            int r = c >> 3, col = (c & 7) * 8;
            cp16(As + r * 72 + col, Ag + (size_t)r * NN + k0 + col);
        }
        if (tid < 64) cp16(Bs + tid * 24, g_z2 + (size_t)(k0 + tid) * 8);
    };

#pragma unroll
    for (int s = 0; s < ST - 1; ++s) { load_tiles(s, kbase + s * KT); cp_commit(); }

    const int NIT = (NN / KSPLIT) / KT;   // 16
    for (int it = 0; it < NIT; ++it) {
        cp_wait_2();
        __syncthreads();
        if (it + ST - 1 < NIT) load_tiles((it + ST - 1) & (ST - 1), kbase + (it + ST - 1) * KT);
        cp_commit();
        int s = it & (ST - 1);
        __nv_bfloat16* As = Abuf + s * 64 * 72;
        __nv_bfloat16* Bs = Bbuf + s * 64 * 24;
#pragma unroll
        for (int ks = 0; ks < 4; ++ks) {
            uint32_t a0, a1, a2, a3, b0, b1r;
            unsigned ad = smem_u32(As + (warp * 16 + (lane & 15)) * 72
                                      + ks * 16 + (lane >> 4) * 8);
            ldmatrix_x4(a0, a1, a2, a3, ad);
            unsigned bd = smem_u32(Bs + (ks * 16 + (lane & 15)) * 24);
            ldmatrix_x2_trans(b0, b1r, bd);
            mma_bf16(acc, a0, a1, a2, a3, b0, b1r);
        }
    }

    if ((lane & 3) == 0) {
        int r = warp * 16 + (lane >> 2);
        g_part[kslice][row0 + r][0] = acc[0];
        g_part[kslice][row0 + r][1] = acc[1];
        g_part[kslice][row0 + r + 8][0] = acc[2];
        g_part[kslice][row0 + r + 8][1] = acc[3];
    }
}

// ---------------------------------------------------------------------------
// Kernel 5: reduce split-K partials: out = d ⊙ (Σ partials) + b2
// ---------------------------------------------------------------------------
__global__ __launch_bounds__(256) void k_reduce(const float* __restrict__ b2,
                                                float* __restrict__ out) {
    int m = blockIdx.x * 256 + threadIdx.x;
    float s0 = 0.f, s1 = 0.f;
#pragma unroll
    for (int s = 0; s < KSPLIT; ++s) {
        s0 += g_part[s][m][0];
        s1 += g_part[s][m][1];
    }
    float dd = g_d[m];
    out[m * 2 + 0] = dd * s0 + b2[0];
    out[m * 2 + 1] = dd * s1 + b2[1];
}

// ---------------------------------------------------------------------------
// Launch
// ---------------------------------------------------------------------------
extern "C" void kernel_launch(void* const* d_in, const int* in_sizes, int n_in,
                              void* d_out, int out_size) {
    const float *x = nullptr, *adj = nullptr, *W1 = nullptr, *b1 = nullptr,
                *W2 = nullptr, *b2 = nullptr;
    for (int i = 0; i < n_in; ++i) {
        switch (in_sizes[i]) {
            case NN * FIN:    x   = (const float*)d_in[i]; break;
            case 67108864:    adj = (const float*)d_in[i]; break;
            case FIN * FHID:  W1  = (const float*)d_in[i]; break;
            case FHID:        b1  = (const float*)d_in[i]; break;
            case FHID * FOUT: W2  = (const float*)d_in[i]; break;
            case FOUT:        b2  = (const float*)d_in[i]; break;
            default: break;
        }
    }
    float* out = (float*)d_out;

    const int smem1 = (ST * A1_STRIDE + ST * B1_STRIDE) * 2;   // 110592 B
    const int smem2 = ST * 64 * 72 * 2 + ST * 64 * 24 * 2;     // 49152 B
    cudaFuncSetAttribute(k_agg1, cudaFuncAttributeMaxDynamicSharedMemorySize, smem1);
    cudaFuncSetAttribute(k_agg2, cudaFuncAttributeMaxDynamicSharedMemorySize, smem2);

    k_rowsum_convert<<<NN, 256>>>(adj);
    k_xw1<<<NN / 16, 256>>>(x, W1);
    k_agg1<<<dim3(NN / 128, KSPLIT1), 256, smem1>>>();
    k_mid<<<NN / 8, 256>>>(b1, W2);
    k_agg2<<<dim3(NN / 64, KSPLIT), 128, smem2>>>();
    k_reduce<<<NN / 256, 256>>>(b2, out);
}

// round 6
// speedup vs baseline: 2.1363x; 1.0371x over previous
#include <cuda_runtime.h>
#include <cuda_bf16.h>
#include <cstdint>

// ---------------------------------------------------------------------------
// Problem constants
// ---------------------------------------------------------------------------
#define NN   8192
#define FIN  128
#define FHID 64
#define FOUT 2
#define KSPLIT  8     // layer-2 aggregation split
#define KSPLIT1 4     // layer-1 aggregation split
#define INV255  (1.0f / 255.0f)

// ---------------------------------------------------------------------------
// Scratch (__device__ globals)
// ---------------------------------------------------------------------------
__device__ unsigned char g_adj8[(size_t)NN * NN];     // 64 MB u8 adjacency (x255)
__device__ float         g_d[NN];                      // d_inv_sqrt
__device__ __nv_bfloat16 g_z1[NN * FHID];              // d ⊙ (x@W1)  [8192,64]
__device__ __nv_bfloat16 g_z2[NN * 8];                 // d ⊙ (h@W2)  [8192,8]
__device__ float         g_part1[KSPLIT1][NN][FHID];   // layer-1 split-K partials
__device__ float         g_part[KSPLIT][NN][2];        // layer-2 split-K partials

// ---------------------------------------------------------------------------
// PTX helpers
// ---------------------------------------------------------------------------
__device__ __forceinline__ unsigned smem_u32(const void* p) {
    return (unsigned)__cvta_generic_to_shared(p);
}
__device__ __forceinline__ void cp16(void* dst, const void* src) {
    unsigned d = smem_u32(dst);
    asm volatile("cp.async.cg.shared.global [%0],[%1],16;\n" :: "r"(d), "l"(src));
}
__device__ __forceinline__ void cp_commit() {
    asm volatile("cp.async.commit_group;\n");
}
__device__ __forceinline__ void cp_wait_2() {
    asm volatile("cp.async.wait_group 2;\n");
}
__device__ __forceinline__ void ldmatrix_x4(uint32_t& a0, uint32_t& a1, uint32_t& a2, uint32_t& a3,
                                            unsigned addr) {
    asm volatile("ldmatrix.sync.aligned.m8n8.x4.shared.b16 {%0,%1,%2,%3},[%4];\n"
                 : "=r"(a0), "=r"(a1), "=r"(a2), "=r"(a3) : "r"(addr));
}
__device__ __forceinline__ void ldmatrix_x2_trans(uint32_t& b0, uint32_t& b1, unsigned addr) {
    asm volatile("ldmatrix.sync.aligned.m8n8.x2.trans.shared.b16 {%0,%1},[%2];\n"
                 : "=r"(b0), "=r"(b1) : "r"(addr));
}
__device__ __forceinline__ void mma_bf16(float c[4],
                                         uint32_t a0, uint32_t a1, uint32_t a2, uint32_t a3,
                                         uint32_t b0, uint32_t b1) {
    asm volatile("mma.sync.aligned.m16n8k16.row.col.f32.bf16.bf16.f32 "
                 "{%0,%1,%2,%3},{%4,%5,%6,%7},{%8,%9},{%0,%1,%2,%3};\n"
                 : "+f"(c[0]), "+f"(c[1]), "+f"(c[2]), "+f"(c[3])
                 : "r"(a0), "r"(a1), "r"(a2), "r"(a3), "r"(b0), "r"(b1));
}
__device__ __forceinline__ unsigned bf2_bits(__nv_bfloat162 v) {
    return *reinterpret_cast<unsigned*>(&v);
}
// 4 packed u8 -> 2 bf16x2 words (values 0..255, exact in bf16)
__device__ __forceinline__ void u8x4_to_bf16x4(uint32_t w, uint32_t& lo, uint32_t& hi) {
    float f0 = (float)(w & 255u);
    float f1 = (float)((w >> 8) & 255u);
    float f2 = (float)((w >> 16) & 255u);
    float f3 = (float)(w >> 24);
    lo = bf2_bits(__floats2bfloat162_rn(f0, f1));
    hi = bf2_bits(__floats2bfloat162_rn(f2, f3));
}

// ---------------------------------------------------------------------------
// Kernel 1: row sums of adj (fp32) + quantize adj -> u8 (x255).
// ---------------------------------------------------------------------------
__global__ __launch_bounds__(256) void k_rowsum_convert(const float* __restrict__ adj) {
    int row = blockIdx.x;
    const float4* src = reinterpret_cast<const float4*>(adj + (size_t)row * NN);
    uint2* dst = reinterpret_cast<uint2*>(g_adj8 + (size_t)row * NN);
    float s = 0.f;
#pragma unroll
    for (int it = 0; it < 4; ++it) {
        int idx = it * 512 + threadIdx.x * 2;
        float4 v0 = __ldcs(src + idx);
        float4 v1 = __ldcs(src + idx + 1);
        s += ((v0.x + v0.y) + (v0.z + v0.w)) + ((v1.x + v1.y) + (v1.z + v1.w));
        uint32_t q0 = __float2uint_rn(v0.x * 255.f)
                    | (__float2uint_rn(v0.y * 255.f) << 8)
                    | (__float2uint_rn(v0.z * 255.f) << 16)
                    | (__float2uint_rn(v0.w * 255.f) << 24);
        uint32_t q1 = __float2uint_rn(v1.x * 255.f)
                    | (__float2uint_rn(v1.y * 255.f) << 8)
                    | (__float2uint_rn(v1.z * 255.f) << 16)
                    | (__float2uint_rn(v1.w * 255.f) << 24);
        dst[idx >> 1] = make_uint2(q0, q1);
    }
    for (int o = 16; o; o >>= 1) s += __shfl_xor_sync(0xFFFFFFFFu, s, o);
    __shared__ float ws[8];
    if ((threadIdx.x & 31) == 0) ws[threadIdx.x >> 5] = s;
    __syncthreads();
    if (threadIdx.x == 0) {
        float t = 0.f;
#pragma unroll
        for (int w = 0; w < 8; ++w) t += ws[w];
        g_d[row] = rsqrtf(t + 1e-6f);
    }
}

// ---------------------------------------------------------------------------
// Kernel 2: z1 = bf16( d ⊙ (x @ W1) ).
// ---------------------------------------------------------------------------
__global__ __launch_bounds__(256) void k_xw1(const float* __restrict__ x,
                                             const float* __restrict__ W1) {
    __shared__ float W1s[FIN][FHID];
    __shared__ float xs[16][FIN];
    int tid = threadIdx.x;
    int r0 = blockIdx.x * 16;
    for (int i = tid; i < FIN * FHID; i += 256) W1s[i >> 6][i & 63] = W1[i];
    for (int i = tid; i < 16 * FIN; i += 256) xs[i >> 7][i & 127] = x[(size_t)r0 * FIN + i];
    __syncthreads();
    int f = tid & 63;
    int rb = tid >> 6;
    float acc[4] = {0.f, 0.f, 0.f, 0.f};
#pragma unroll
    for (int k = 0; k < FIN; ++k) {
        float w = W1s[k][f];
#pragma unroll
        for (int j = 0; j < 4; ++j) acc[j] += xs[rb + j * 4][k] * w;
    }
#pragma unroll
    for (int j = 0; j < 4; ++j) {
        int row = r0 + rb + j * 4;
        g_z1[row * FHID + f] = __float2bfloat16(g_d[row] * acc[j]);
    }
}

// ---------------------------------------------------------------------------
// Kernel 3: agg1 split-K on u8 adjacency.
//   g_part1[ksl] = (1/255) * adj8[:, kslice] @ z1[kslice, :]
// CTA tile 128x64, KT=64, 4-stage cp.async on u8 A + bf16 B; per-iteration
// in-smem dequant u8 -> bf16 into a double-buffered ldmatrix-ready tile.
// smem: A8 [4][8192]B =32KB | Wb [2][128][72]bf16 =36KB | B [4][64][72]bf16 =36KB
// ---------------------------------------------------------------------------
#define KT 64
#define ST 4
#define A1_STAGE (128 * 64)          // bytes per u8 A stage (flat)
#define W1_STRIDE (128 * 72)         // bf16 elems per converted buffer
#define B1_STRIDE (64 * 72)

__global__ __launch_bounds__(256) void k_agg1() {
    extern __shared__ __align__(16) unsigned char dyn[];
    unsigned char* A8 = dyn;                                          // [ST][A1_STAGE]
    __nv_bfloat16* Wb = reinterpret_cast<__nv_bfloat16*>(dyn + ST * A1_STAGE);   // [2][128][72]
    __nv_bfloat16* Bb = Wb + 2 * W1_STRIDE;                           // [ST][64][72]

    int tid = threadIdx.x;
    int warp = tid >> 5, lane = tid & 31;
    int wm = warp >> 1, wn = warp & 1;            // 4m x 2n warp grid
    int row0 = blockIdx.x * 128;
    int ksl = blockIdx.y;
    int kbase = ksl * (NN / KSPLIT1);             // 2048
    float acc[2][4][4] = {};
    const unsigned char* Ag = g_adj8 + (size_t)row0 * NN;

    auto load_tiles = [&](int s, int k0) {
        unsigned char* As = A8 + s * A1_STAGE;
        __nv_bfloat16* Bs = Bb + s * B1_STRIDE;
#pragma unroll
        for (int i = 0; i < 2; ++i) {             // A: 128 rows x 64B = 512 chunks
            int c = tid + i * 256;
            int r = c >> 2, col = (c & 3) * 16;
            cp16(As + r * 64 + col, Ag + (size_t)r * NN + k0 + col);
        }
#pragma unroll
        for (int i = 0; i < 2; ++i) {             // B: 64 rows x 128B = 512 chunks
            int c = tid + i * 256;
            int r = c >> 3, col = (c & 7) * 8;
            cp16(Bs + r * 72 + col, g_z1 + (size_t)(k0 + r) * FHID + col);
        }
    };

#pragma unroll
    for (int s = 0; s < ST - 1; ++s) { load_tiles(s, kbase + s * KT); cp_commit(); }

    const int NIT = (NN / KSPLIT1) / KT;   // 32
    for (int it = 0; it < NIT; ++it) {
        cp_wait_2();
        __syncthreads();
        if (it + ST - 1 < NIT) load_tiles((it + ST - 1) & (ST - 1), kbase + (it + ST - 1) * KT);
        cp_commit();

        // dequant stage s -> Wb[it&1]; lanes read consecutive 8B (conflict-free)
        int s = it & (ST - 1);
        {
            const uint2* sflat = reinterpret_cast<const uint2*>(A8 + s * A1_STAGE);
            __nv_bfloat16* W = Wb + (it & 1) * W1_STRIDE;
#pragma unroll
            for (int j = 0; j < 4; ++j) {
                int e0 = warp * 1024 + j * 256 + lane * 8;    // flat elem index
                uint2 w = sflat[e0 >> 3];
                int r = e0 >> 6, col = e0 & 63;
                uint32_t o0, o1, o2, o3;
                u8x4_to_bf16x4(w.x, o0, o1);
                u8x4_to_bf16x4(w.y, o2, o3);
                *reinterpret_cast<uint4*>(W + r * 72 + col) = make_uint4(o0, o1, o2, o3);
            }
        }
        __syncthreads();

        __nv_bfloat16* As = Wb + (it & 1) * W1_STRIDE;
        __nv_bfloat16* Bs = Bb + s * B1_STRIDE;
#pragma unroll
        for (int ks = 0; ks < 4; ++ks) {
            uint32_t a[2][4], b[4][2];
#pragma unroll
            for (int mt = 0; mt < 2; ++mt) {
                unsigned ad = smem_u32(As + (wm * 32 + mt * 16 + (lane & 15)) * 72
                                          + ks * 16 + (lane >> 4) * 8);
                ldmatrix_x4(a[mt][0], a[mt][1], a[mt][2], a[mt][3], ad);
            }
#pragma unroll
            for (int nt = 0; nt < 4; ++nt) {
                unsigned bd = smem_u32(Bs + (ks * 16 + (lane & 15)) * 72 + wn * 32 + nt * 8);
                ldmatrix_x2_trans(b[nt][0], b[nt][1], bd);
            }
#pragma unroll
            for (int mt = 0; mt < 2; ++mt)
#pragma unroll
                for (int nt = 0; nt < 4; ++nt)
                    mma_bf16(acc[mt][nt], a[mt][0], a[mt][1], a[mt][2], a[mt][3],
                             b[nt][0], b[nt][1]);
        }
    }

    // write fp32 partials, folding the 1/255 dequant scale
#pragma unroll
    for (int mt = 0; mt < 2; ++mt) {
#pragma unroll
        for (int nt = 0; nt < 4; ++nt) {
            int cbase = wn * 32 + nt * 8 + (lane & 3) * 2;
#pragma unroll
            for (int half = 0; half < 2; ++half) {
                int r = wm * 32 + mt * 16 + (lane >> 2) + half * 8;
                float2 v = make_float2(acc[mt][nt][half * 2 + 0] * INV255,
                                       acc[mt][nt][half * 2 + 1] * INV255);
                *reinterpret_cast<float2*>(&g_part1[ksl][row0 + r][cbase]) = v;
            }
        }
    }
}

// ---------------------------------------------------------------------------
// Kernel 3b: mid epilogue.  h = relu(d*ΣU+b1); z2 = bf16(d ⊙ (h@W2)).
// 8 cols per thread via float4; 8 lanes per row; 32 rows per block.
// ---------------------------------------------------------------------------
__global__ __launch_bounds__(256) void k_mid(const float* __restrict__ b1,
                                             const float* __restrict__ W2) {
    int tid = threadIdx.x;
    int seg = tid & 7;                     // 8 threads per row
    int row = blockIdx.x * 32 + (tid >> 3);
    float dd = g_d[row];
    float u[8] = {};
#pragma unroll
    for (int s = 0; s < KSPLIT1; ++s) {
        float4 a = *reinterpret_cast<const float4*>(&g_part1[s][row][seg * 8]);
        float4 b = *reinterpret_cast<const float4*>(&g_part1[s][row][seg * 8 + 4]);
        u[0] += a.x; u[1] += a.y; u[2] += a.z; u[3] += a.w;
        u[4] += b.x; u[5] += b.y; u[6] += b.z; u[7] += b.w;
    }
    float s0 = 0.f, s1 = 0.f;
#pragma unroll
    for (int j = 0; j < 8; ++j) {
        int c = seg * 8 + j;
        float h = fmaxf(dd * u[j] + b1[c], 0.f);
        s0 += h * W2[c * 2 + 0];
        s1 += h * W2[c * 2 + 1];
    }
    for (int o = 4; o; o >>= 1) {
        s0 += __shfl_xor_sync(0xFFFFFFFFu, s0, o);
        s1 += __shfl_xor_sync(0xFFFFFFFFu, s1, o);
    }
    if (seg == 0) {
        uint4 o;
        o.x = bf2_bits(__floats2bfloat162_rn(dd * s0, dd * s1));
        o.y = 0u; o.z = 0u; o.w = 0u;
        *reinterpret_cast<uint4*>(&g_z2[(size_t)row * 8]) = o;
    }
}

// ---------------------------------------------------------------------------
// Kernel 4: agg2 split-K on u8 adjacency.
//   g_part[ksl] = (1/255) * adj8[:, kslice] @ z2[kslice, :]
// M_TILE=64, KT=64, same staged-dequant scheme, 4 warps / 128 threads.
// smem: A8 [4][4096]B =16KB | Wb [2][64][72] =18KB | B [4][64][24] =12KB
// ---------------------------------------------------------------------------
#define A2_STAGE (64 * 64)
#define W2_STRIDE (64 * 72)

__global__ __launch_bounds__(128) void k_agg2() {
    extern __shared__ __align__(16) unsigned char dyn[];
    unsigned char* A8 = dyn;                                           // [ST][A2_STAGE]
    __nv_bfloat16* Wb = reinterpret_cast<__nv_bfloat16*>(dyn + ST * A2_STAGE);  // [2][64][72]
    __nv_bfloat16* Bb = Wb + 2 * W2_STRIDE;                            // [ST][64][24]

    int tid = threadIdx.x, warp = tid >> 5, lane = tid & 31;
    int row0 = blockIdx.x * 64;
    int kslice = blockIdx.y;
    int kbase = kslice * (NN / KSPLIT);   // 1024
    float acc[4] = {0.f, 0.f, 0.f, 0.f};
    const unsigned char* Ag = g_adj8 + (size_t)row0 * NN;

    auto load_tiles = [&](int s, int k0) {
        unsigned char* As = A8 + s * A2_STAGE;
        __nv_bfloat16* Bs = Bb + s * 64 * 24;
#pragma unroll
        for (int i = 0; i < 2; ++i) {             // A: 64 rows x 64B = 256 chunks
            int c = tid + i * 128;
            int r = c >> 2, col = (c & 3) * 16;
            cp16(As + r * 64 + col, Ag + (size_t)r * NN + k0 + col);
        }
        if (tid < 64) cp16(Bs + tid * 24, g_z2 + (size_t)(k0 + tid) * 8);
    };

#pragma unroll
    for (int s = 0; s < ST - 1; ++s) { load_tiles(s, kbase + s * KT); cp_commit(); }

    const int NIT = (NN / KSPLIT) / KT;   // 16
    for (int it = 0; it < NIT; ++it) {
        cp_wait_2();
        __syncthreads();
        if (it + ST - 1 < NIT) load_tiles((it + ST - 1) & (ST - 1), kbase + (it + ST - 1) * KT);
        cp_commit();

        int s = it & (ST - 1);
        {
            const uint2* sflat = reinterpret_cast<const uint2*>(A8 + s * A2_STAGE);
            __nv_bfloat16* W = Wb + (it & 1) * W2_STRIDE;
#pragma unroll
            for (int j = 0; j < 4; ++j) {
                int e0 = warp * 1024 + j * 256 + lane * 8;
                uint2 w = sflat[e0 >> 3];
                int r = e0 >> 6, col = e0 & 63;
                uint32_t o0, o1, o2, o3;
                u8x4_to_bf16x4(w.x, o0, o1);
                u8x4_to_bf16x4(w.y, o2, o3);
                *reinterpret_cast<uint4*>(W + r * 72 + col) = make_uint4(o0, o1, o2, o3);
            }
        }
        __syncthreads();

        __nv_bfloat16* As = Wb + (it & 1) * W2_STRIDE;
        __nv_bfloat16* Bs = Bb + s * 64 * 24;
#pragma unroll
        for (int ks = 0; ks < 4; ++ks) {
            uint32_t a0, a1, a2, a3, b0, b1r;
            unsigned ad = smem_u32(As + (warp * 16 + (lane & 15)) * 72
                                      + ks * 16 + (lane >> 4) * 8);
            ldmatrix_x4(a0, a1, a2, a3, ad);
            unsigned bd = smem_u32(Bs + (ks * 16 + (lane & 15)) * 24);
            ldmatrix_x2_trans(b0, b1r, bd);
            mma_bf16(acc, a0, a1, a2, a3, b0, b1r);
        }
    }

    if ((lane & 3) == 0) {
        int r = warp * 16 + (lane >> 2);
        g_part[kslice][row0 + r][0] = acc[0] * INV255;
        g_part[kslice][row0 + r][1] = acc[1] * INV255;
        g_part[kslice][row0 + r + 8][0] = acc[2] * INV255;
        g_part[kslice][row0 + r + 8][1] = acc[3] * INV255;
    }
}

// ---------------------------------------------------------------------------
// Kernel 5: reduce split-K partials: out = d ⊙ (Σ partials) + b2
// ---------------------------------------------------------------------------
__global__ __launch_bounds__(256) void k_reduce(const float* __restrict__ b2,
                                                float* __restrict__ out) {
    int m = blockIdx.x * 256 + threadIdx.x;
    float s0 = 0.f, s1 = 0.f;
#pragma unroll
    for (int s = 0; s < KSPLIT; ++s) {
        s0 += g_part[s][m][0];
        s1 += g_part[s][m][1];
    }
    float dd = g_d[m];
    out[m * 2 + 0] = dd * s0 + b2[0];
    out[m * 2 + 1] = dd * s1 + b2[1];
}

// ---------------------------------------------------------------------------
// Launch
// ---------------------------------------------------------------------------
extern "C" void kernel_launch(void* const* d_in, const int* in_sizes, int n_in,
                              void* d_out, int out_size) {
    const float *x = nullptr, *adj = nullptr, *W1 = nullptr, *b1 = nullptr,
                *W2 = nullptr, *b2 = nullptr;
    for (int i = 0; i < n_in; ++i) {
        switch (in_sizes[i]) {
            case NN * FIN:    x   = (const float*)d_in[i]; break;
            case 67108864:    adj = (const float*)d_in[i]; break;
            case FIN * FHID:  W1  = (const float*)d_in[i]; break;
            case FHID:        b1  = (const float*)d_in[i]; break;
            case FHID * FOUT: W2  = (const float*)d_in[i]; break;
            case FOUT:        b2  = (const float*)d_in[i]; break;
            default: break;
        }
    }
    float* out = (float*)d_out;

    const int smem1 = ST * A1_STAGE + 2 * W1_STRIDE * 2 + ST * B1_STRIDE * 2;  // 106496
    const int smem2 = ST * A2_STAGE + 2 * W2_STRIDE * 2 + ST * 64 * 24 * 2;    // 47104
    cudaFuncSetAttribute(k_agg1, cudaFuncAttributeMaxDynamicSharedMemorySize, smem1);
    cudaFuncSetAttribute(k_agg2, cudaFuncAttributeMaxDynamicSharedMemorySize, smem2);

    k_rowsum_convert<<<NN, 256>>>(adj);
    k_xw1<<<NN / 16, 256>>>(x, W1);
    k_agg1<<<dim3(NN / 128, KSPLIT1), 256, smem1>>>();
    k_mid<<<NN / 32, 256>>>(b1, W2);
    k_agg2<<<dim3(NN / 64, KSPLIT), 128, smem2>>>();
    k_reduce<<<NN / 256, 256>>>(b2, out);
}